// round 10
// baseline (speedup 1.0000x reference)
#include <cuda_runtime.h>
#include <stdint.h>

#define Bn 32
#define Nn 512
#define Pn 128

// Scratch (static device globals: allocation-free)
__device__ float g_mwh[Bn * Nn * Pn];  // tf32-rounded hi of mu@W2 (8 MB)
__device__ float g_mwl[Bn * Nn * Pn];  // tf32-rounded residual     (8 MB)
__device__ float g_vp[Pn];
__device__ float g_vn[Pn];
__device__ float g_cb[Pn];             // b1 + b2 + b3

// ---- packed f32x2 helpers (PTX-only packed-FP32 pipe) ---------------------
__device__ __forceinline__ void fma2(unsigned long long& d,
                                     unsigned long long a,
                                     unsigned long long b) {
    asm("fma.rn.f32x2 %0, %1, %2, %3;" : "=l"(d) : "l"(a), "l"(b), "l"(d));
}
__device__ __forceinline__ unsigned long long rep2(float a) {
    unsigned long long p;
    asm("mov.b64 %0, {%1, %1};" : "=l"(p) : "f"(a));
    return p;
}
__device__ __forceinline__ float2 unpack2(unsigned long long p) {
    float2 r;
    asm("mov.b64 {%0, %1}, %2;" : "=f"(r.x), "=f"(r.y) : "l"(p));
    return r;
}
__device__ __forceinline__ float tf32_round(float v) {
    uint32_t u;
    asm("cvt.rna.tf32.f32 %0, %1;" : "=r"(u) : "f"(v));
    return __uint_as_float(u);
}

// ---- tf32 mma m16n8k8: D(fp32) += A(tf32) @ B(tf32) -----------------------
__device__ __forceinline__ void mma_tf32(float* c, const uint32_t* a,
                                         uint32_t b0, uint32_t b1) {
    asm volatile(
        "mma.sync.aligned.m16n8k8.row.col.f32.tf32.tf32.f32 "
        "{%0,%1,%2,%3}, {%4,%5,%6,%7}, {%8,%9}, {%0,%1,%2,%3};"
        : "+f"(c[0]), "+f"(c[1]), "+f"(c[2]), "+f"(c[3])
        : "r"(a[0]), "r"(a[1]), "r"(a[2]), "r"(a[3]), "r"(b0), "r"(b1));
}

// ---------------------------------------------------------------------------
// Phase 1: mu @ W2 (f32x2 GEMM), output split into tf32 hi/lo. Last CTA: prep.
// ---------------------------------------------------------------------------
__global__ __launch_bounds__(256) void mw_kernel(const float* __restrict__ mu,
                                                 const float* __restrict__ W2,
                                                 const float* __restrict__ W3,
                                                 const float* __restrict__ theta4,
                                                 const float* __restrict__ b1,
                                                 const float* __restrict__ b2,
                                                 const float* __restrict__ b3) {
    if (blockIdx.x == gridDim.x - 1) {
        int p = threadIdx.x;
        if (p < Pn) {
            float vp = 0.f, vn = 0.f;
            #pragma unroll 8
            for (int q = 0; q < Pn; ++q) {
                float t = theta4[q];
                float w = W3[q * Pn + p];
                vp += fmaxf(t, 0.f) * w;
                vn += fmaxf(-t, 0.f) * w;
            }
            g_vp[p] = vp;
            g_vn[p] = vn;
            g_cb[p] = b1[p] + b2[p] + b3[p];
        }
        return;
    }

    __shared__ float As[32 * 68];
    __shared__ float Bs[32 * 128];

    int tid = threadIdx.x;
    int tx = tid & 15;
    int ty = tid >> 4;
    int r0 = blockIdx.x * 64;

    unsigned long long acc2[4][4];
    #pragma unroll
    for (int u = 0; u < 4; ++u)
        #pragma unroll
        for (int q = 0; q < 4; ++q) acc2[u][q] = 0ull;

    for (int kb = 0; kb < 4; ++kb) {
        int k0 = kb * 32;
        #pragma unroll
        for (int s = 0; s < 2; ++s) {
            int idx = tid + s * 256;
            int m = idx >> 3;
            int kq = idx & 7;
            float4 f = *(const float4*)&mu[(r0 + m) * Pn + k0 + kq * 4];
            As[(kq * 4 + 0) * 68 + m] = f.x;
            As[(kq * 4 + 1) * 68 + m] = f.y;
            As[(kq * 4 + 2) * 68 + m] = f.z;
            As[(kq * 4 + 3) * 68 + m] = f.w;
        }
        #pragma unroll
        for (int s = 0; s < 4; ++s) {
            int idx = tid + s * 256;
            int k = idx >> 5;
            int c = idx & 31;
            *(float4*)&Bs[k * 128 + c * 4] =
                *(const float4*)&W2[(k0 + k) * Pn + c * 4];
        }
        __syncthreads();

        #pragma unroll
        for (int k = 0; k < 32; ++k) {
            float4 a4 = *(const float4*)&As[k * 68 + ty * 4];
            ulonglong2 B0 = *(const ulonglong2*)&Bs[k * 128 + tx * 8];
            ulonglong2 B1 = *(const ulonglong2*)&Bs[k * 128 + tx * 8 + 4];
            unsigned long long pa[4] = {rep2(a4.x), rep2(a4.y), rep2(a4.z), rep2(a4.w)};
            #pragma unroll
            for (int u = 0; u < 4; ++u) {
                fma2(acc2[u][0], pa[u], B0.x);
                fma2(acc2[u][1], pa[u], B0.y);
                fma2(acc2[u][2], pa[u], B1.x);
                fma2(acc2[u][3], pa[u], B1.y);
            }
        }
        __syncthreads();
    }

    #pragma unroll
    for (int u = 0; u < 4; ++u) {
        int row = r0 + ty * 4 + u;
        float v[8], h[8], l[8];
        #pragma unroll
        for (int q = 0; q < 4; ++q) {
            float2 t = unpack2(acc2[u][q]);
            v[q * 2] = t.x;
            v[q * 2 + 1] = t.y;
        }
        #pragma unroll
        for (int q = 0; q < 8; ++q) {
            h[q] = tf32_round(v[q]);
            l[q] = tf32_round(v[q] - h[q]);
        }
        float4 h0 = make_float4(h[0], h[1], h[2], h[3]);
        float4 h1 = make_float4(h[4], h[5], h[6], h[7]);
        float4 l0 = make_float4(l[0], l[1], l[2], l[3]);
        float4 l1 = make_float4(l[4], l[5], l[6], l[7]);
        *(float4*)&g_mwh[row * Pn + tx * 8]     = h0;
        *(float4*)&g_mwh[row * Pn + tx * 8 + 4] = h1;
        *(float4*)&g_mwl[row * Pn + tx * 8]     = l0;
        *(float4*)&g_mwl[row * Pn + tx * 8 + 4] = l1;
    }
}

// ---------------------------------------------------------------------------
// Phase 2: tensor-core aggregation. C[64 j][128 p] = adj[j][:] @ (mwh+mwl),
// fused pos/neg (masked relu of weight, adj mask from staged A tile) + epilogue.
// Grid (8 j-tiles, 32 b) = 256 CTAs x 256 threads (8 warps: 2 M x 4 N).
// smem ~46 KB -> 2 CTA/SM, single wave.
// ---------------------------------------------------------------------------
__global__ __launch_bounds__(256, 2) void agg_mma_kernel(
    const float* __restrict__ adj, const float* __restrict__ weight,
    const float* __restrict__ x, const float* __restrict__ W1,
    float* __restrict__ out) {
    extern __shared__ float sm[];
    float* As   = sm;                 // [64][33]  adj tile (j-major)
    float* Bh   = sm + 2112;          // [128][33] mwh transposed (p-major)
    float* Bl   = sm + 6336;          // [128][33] mwl transposed
    float* W1s  = sm + 10560;         // 128
    float* vps  = sm + 10688;
    float* vns  = sm + 10816;
    float* cbs  = sm + 10944;
    float* pnb  = sm + 11072;         // [8][64] pos/neg partials
    float* posS = sm + 11584;         // 64
    float* negS = sm + 11648;         // 64

    int tid = threadIdx.x;
    int warp = tid >> 5;
    int lane = tid & 31;
    int warpM = warp >> 2;            // 0..1 -> j offset 32*warpM
    int warpN = warp & 3;             // 0..3 -> p offset 32*warpN
    int g4 = lane >> 2;               // 0..7
    int t4 = lane & 3;                // 0..3
    int b = blockIdx.y;
    int j0 = blockIdx.x * 64;

    if (tid < 128) {
        W1s[tid] = W1[tid];
        vps[tid] = g_vp[tid];
        vns[tid] = g_vn[tid];
        cbs[tid] = g_cb[tid];
    }

    const float* adj_b = adj + (size_t)b * Nn * Nn;
    const float* w_b   = weight + (size_t)b * Nn * Nn;
    const float* mwh_b = g_mwh + (size_t)b * Nn * Pn;
    const float* mwl_b = g_mwl + (size_t)b * Nn * Pn;

    // pos/neg mapping: thread owns column jj, k-subgroup ks (8 k's per chunk)
    int jj = tid & 63;
    int ks = tid >> 6;                // 0..3

    float C[2][4][4];
    #pragma unroll
    for (int mt = 0; mt < 2; ++mt)
        #pragma unroll
        for (int nt = 0; nt < 4; ++nt)
            #pragma unroll
            for (int c = 0; c < 4; ++c) C[mt][nt][c] = 0.f;
    float posr = 0.f, negr = 0.f;

    for (int chunk = 0; chunk < 16; ++chunk) {
        int k0 = chunk * 32;
        __syncthreads();   // smem reuse (covers const staging on iter 0)

        // Stage A: adj[j0+row][k0..k0+32), 64 rows (coalesced 128B rows)
        #pragma unroll
        for (int s = 0; s < 2; ++s) {
            int idx = tid + s * 256;           // 0..511
            int row = idx >> 3;
            int q = idx & 7;
            float4 a = *(const float4*)&adj_b[(size_t)(j0 + row) * Nn + k0 + q * 4];
            float* dst = &As[row * 33 + q * 4];
            dst[0] = a.x; dst[1] = a.y; dst[2] = a.z; dst[3] = a.w;
        }
        // Stage Bh/Bl transposed: [k][p] global -> [p][33] smem
        #pragma unroll
        for (int s = 0; s < 4; ++s) {
            int idx = tid + s * 256;           // 0..1023
            int k = idx >> 5;
            int p4 = (idx & 31) << 2;
            float4 h = *(const float4*)&mwh_b[(k0 + k) * Pn + p4];
            float4 l = *(const float4*)&mwl_b[(k0 + k) * Pn + p4];
            Bh[(p4 + 0) * 33 + k] = h.x;
            Bh[(p4 + 1) * 33 + k] = h.y;
            Bh[(p4 + 2) * 33 + k] = h.z;
            Bh[(p4 + 3) * 33 + k] = h.w;
            Bl[(p4 + 0) * 33 + k] = l.x;
            Bl[(p4 + 1) * 33 + k] = l.y;
            Bl[(p4 + 2) * 33 + k] = l.z;
            Bl[(p4 + 3) * 33 + k] = l.w;
        }
        __syncthreads();

        // pos/neg: w coalesced rows; adj mask via transposed As read (stride 33)
        #pragma unroll
        for (int s = 0; s < 8; ++s) {
            int k = ks * 8 + s;
            float w = w_b[(size_t)(k0 + k) * Nn + j0 + jj];
            float a = As[jj * 33 + k];          // exactly 0.0 or 1.0
            posr += a * fmaxf(w, 0.f);
            negr += a * fmaxf(-w, 0.f);
        }

        // MMA mainloop: 4 k8 steps
        #pragma unroll
        for (int kk = 0; kk < 4; ++kk) {
            int kb = kk * 8;
            uint32_t afr[2][4];
            #pragma unroll
            for (int mt = 0; mt < 2; ++mt) {
                int r = warpM * 32 + mt * 16 + g4;
                int c = kb + t4;
                afr[mt][0] = __float_as_uint(As[r * 33 + c]);
                afr[mt][1] = __float_as_uint(As[(r + 8) * 33 + c]);
                afr[mt][2] = __float_as_uint(As[r * 33 + c + 4]);
                afr[mt][3] = __float_as_uint(As[(r + 8) * 33 + c + 4]);
            }
            #pragma unroll
            for (int nt = 0; nt < 4; ++nt) {
                int p = warpN * 32 + nt * 8 + g4;
                int c = kb + t4;
                uint32_t bh0 = __float_as_uint(Bh[p * 33 + c]);
                uint32_t bh1 = __float_as_uint(Bh[p * 33 + c + 4]);
                uint32_t bl0 = __float_as_uint(Bl[p * 33 + c]);
                uint32_t bl1 = __float_as_uint(Bl[p * 33 + c + 4]);
                #pragma unroll
                for (int mt = 0; mt < 2; ++mt) {
                    mma_tf32(C[mt][nt], afr[mt], bh0, bh1);
                    mma_tf32(C[mt][nt], afr[mt], bl0, bl1);
                }
            }
        }
    }

    // pos/neg reduction (deterministic order)
    __syncthreads();
    pnb[ks * 64 + jj]       = posr;
    pnb[256 + ks * 64 + jj] = negr;
    __syncthreads();
    if (tid < 64) {
        posS[tid] = ((pnb[tid] + pnb[64 + tid]) + (pnb[128 + tid] + pnb[192 + tid]));
    } else if (tid < 128) {
        int j = tid - 64;
        negS[j] = ((pnb[256 + j] + pnb[320 + j]) + (pnb[384 + j] + pnb[448 + j]));
    }
    __syncthreads();

    // Epilogue: out = relu(x*W1 + C + pos*vp + neg*vn + cb)
    #pragma unroll
    for (int mt = 0; mt < 2; ++mt) {
        #pragma unroll
        for (int half = 0; half < 2; ++half) {
            int j = warpM * 32 + mt * 16 + g4 + half * 8;
            int gj = j0 + j;
            float xv = x[b * Nn + gj];
            float pj = posS[j];
            float nj = negS[j];
            #pragma unroll
            for (int nt = 0; nt < 4; ++nt) {
                int p = warpN * 32 + nt * 8 + 2 * t4;
                float c0 = C[mt][nt][half * 2 + 0];
                float c1 = C[mt][nt][half * 2 + 1];
                float2 o;
                o.x = fmaxf(xv * W1s[p] + c0 + pj * vps[p] + nj * vns[p] + cbs[p], 0.f);
                o.y = fmaxf(xv * W1s[p + 1] + c1 + pj * vps[p + 1] + nj * vns[p + 1] + cbs[p + 1], 0.f);
                *(float2*)&out[((size_t)b * Nn + gj) * Pn + p] = o;
            }
        }
    }
}

// ---------------------------------------------------------------------------
extern "C" void kernel_launch(void* const* d_in, const int* in_sizes, int n_in,
                              void* d_out, int out_size) {
    const float* x      = (const float*)d_in[0];
    const float* mu     = (const float*)d_in[1];
    const float* weight = (const float*)d_in[2];
    const float* adj    = (const float*)d_in[3];
    const float* W1     = (const float*)d_in[4];
    const float* b1     = (const float*)d_in[5];
    const float* W2     = (const float*)d_in[6];
    const float* b2     = (const float*)d_in[7];
    const float* W3     = (const float*)d_in[8];
    const float* b3     = (const float*)d_in[9];
    const float* theta4 = (const float*)d_in[10];
    float* out = (float*)d_out;

    const int smem_bytes = 11712 * 4;   // 46848 B
    mw_kernel<<<Bn * Nn / 64 + 1, 256>>>(mu, W2, W3, theta4, b1, b2, b3);
    dim3 grid(Nn / 64, Bn);
    agg_mma_kernel<<<grid, 256, smem_bytes>>>(adj, weight, x, W1, out);
}

// round 11
// speedup vs baseline: 1.6542x; 1.6542x over previous
#include <cuda_runtime.h>
#include <stdint.h>

#define Bn 32
#define Nn 512
#define Pn 128

// Scratch (static device globals: allocation-free)
__device__ float g_mwh[Bn * Nn * Pn];  // tf32-rounded hi of mu@W2 (8 MB)
__device__ float g_mwl[Bn * Nn * Pn];  // tf32-rounded residual     (8 MB)
__device__ float g_vp[Pn];
__device__ float g_vn[Pn];
__device__ float g_cb[Pn];             // b1 + b2 + b3

// ---- packed f32x2 helpers (PTX-only packed-FP32 pipe) ---------------------
__device__ __forceinline__ void fma2(unsigned long long& d,
                                     unsigned long long a,
                                     unsigned long long b) {
    asm("fma.rn.f32x2 %0, %1, %2, %3;" : "=l"(d) : "l"(a), "l"(b), "l"(d));
}
__device__ __forceinline__ unsigned long long rep2(float a) {
    unsigned long long p;
    asm("mov.b64 %0, {%1, %1};" : "=l"(p) : "f"(a));
    return p;
}
__device__ __forceinline__ float2 unpack2(unsigned long long p) {
    float2 r;
    asm("mov.b64 {%0, %1}, %2;" : "=f"(r.x), "=f"(r.y) : "l"(p));
    return r;
}
__device__ __forceinline__ float tf32_round(float v) {
    uint32_t u;
    asm("cvt.rna.tf32.f32 %0, %1;" : "=r"(u) : "f"(v));
    return __uint_as_float(u);
}

// ---- tf32 mma m16n8k8: D(fp32) += A(tf32) @ B(tf32) -----------------------
__device__ __forceinline__ void mma_tf32(float* c, const uint32_t* a,
                                         uint32_t b0, uint32_t b1) {
    asm volatile(
        "mma.sync.aligned.m16n8k8.row.col.f32.tf32.tf32.f32 "
        "{%0,%1,%2,%3}, {%4,%5,%6,%7}, {%8,%9}, {%0,%1,%2,%3};"
        : "+f"(c[0]), "+f"(c[1]), "+f"(c[2]), "+f"(c[3])
        : "r"(a[0]), "r"(a[1]), "r"(a[2]), "r"(a[3]), "r"(b0), "r"(b1));
}

// ---- cp.async 16B ---------------------------------------------------------
__device__ __forceinline__ void cpasync16(uint32_t dst, const void* src) {
    asm volatile("cp.async.cg.shared.global [%0], [%1], 16;"
                 :: "r"(dst), "l"(src));
}
__device__ __forceinline__ void cpasync_commit() {
    asm volatile("cp.async.commit_group;");
}

// ---------------------------------------------------------------------------
// Phase 1: mu @ W2 (f32x2 GEMM), output split into tf32 hi/lo. Last CTA: prep.
// ---------------------------------------------------------------------------
__global__ __launch_bounds__(256) void mw_kernel(const float* __restrict__ mu,
                                                 const float* __restrict__ W2,
                                                 const float* __restrict__ W3,
                                                 const float* __restrict__ theta4,
                                                 const float* __restrict__ b1,
                                                 const float* __restrict__ b2,
                                                 const float* __restrict__ b3) {
    if (blockIdx.x == gridDim.x - 1) {
        int p = threadIdx.x;
        if (p < Pn) {
            float vp = 0.f, vn = 0.f;
            #pragma unroll 8
            for (int q = 0; q < Pn; ++q) {
                float t = theta4[q];
                float w = W3[q * Pn + p];
                vp += fmaxf(t, 0.f) * w;
                vn += fmaxf(-t, 0.f) * w;
            }
            g_vp[p] = vp;
            g_vn[p] = vn;
            g_cb[p] = b1[p] + b2[p] + b3[p];
        }
        return;
    }

    __shared__ float As[32 * 68];
    __shared__ float Bs[32 * 128];

    int tid = threadIdx.x;
    int tx = tid & 15;
    int ty = tid >> 4;
    int r0 = blockIdx.x * 64;

    unsigned long long acc2[4][4];
    #pragma unroll
    for (int u = 0; u < 4; ++u)
        #pragma unroll
        for (int q = 0; q < 4; ++q) acc2[u][q] = 0ull;

    for (int kb = 0; kb < 4; ++kb) {
        int k0 = kb * 32;
        #pragma unroll
        for (int s = 0; s < 2; ++s) {
            int idx = tid + s * 256;
            int m = idx >> 3;
            int kq = idx & 7;
            float4 f = *(const float4*)&mu[(r0 + m) * Pn + k0 + kq * 4];
            As[(kq * 4 + 0) * 68 + m] = f.x;
            As[(kq * 4 + 1) * 68 + m] = f.y;
            As[(kq * 4 + 2) * 68 + m] = f.z;
            As[(kq * 4 + 3) * 68 + m] = f.w;
        }
        #pragma unroll
        for (int s = 0; s < 4; ++s) {
            int idx = tid + s * 256;
            int k = idx >> 5;
            int c = idx & 31;
            *(float4*)&Bs[k * 128 + c * 4] =
                *(const float4*)&W2[(k0 + k) * Pn + c * 4];
        }
        __syncthreads();

        #pragma unroll
        for (int k = 0; k < 32; ++k) {
            float4 a4 = *(const float4*)&As[k * 68 + ty * 4];
            ulonglong2 B0 = *(const ulonglong2*)&Bs[k * 128 + tx * 8];
            ulonglong2 B1 = *(const ulonglong2*)&Bs[k * 128 + tx * 8 + 4];
            unsigned long long pa[4] = {rep2(a4.x), rep2(a4.y), rep2(a4.z), rep2(a4.w)};
            #pragma unroll
            for (int u = 0; u < 4; ++u) {
                fma2(acc2[u][0], pa[u], B0.x);
                fma2(acc2[u][1], pa[u], B0.y);
                fma2(acc2[u][2], pa[u], B1.x);
                fma2(acc2[u][3], pa[u], B1.y);
            }
        }
        __syncthreads();
    }

    #pragma unroll
    for (int u = 0; u < 4; ++u) {
        int row = r0 + ty * 4 + u;
        float v[8], h[8], l[8];
        #pragma unroll
        for (int q = 0; q < 4; ++q) {
            float2 t = unpack2(acc2[u][q]);
            v[q * 2] = t.x;
            v[q * 2 + 1] = t.y;
        }
        #pragma unroll
        for (int q = 0; q < 8; ++q) {
            h[q] = tf32_round(v[q]);
            l[q] = tf32_round(v[q] - h[q]);
        }
        *(float4*)&g_mwh[row * Pn + tx * 8]     = make_float4(h[0], h[1], h[2], h[3]);
        *(float4*)&g_mwh[row * Pn + tx * 8 + 4] = make_float4(h[4], h[5], h[6], h[7]);
        *(float4*)&g_mwl[row * Pn + tx * 8]     = make_float4(l[0], l[1], l[2], l[3]);
        *(float4*)&g_mwl[row * Pn + tx * 8 + 4] = make_float4(l[4], l[5], l[6], l[7]);
    }
}

// ---------------------------------------------------------------------------
// Phase 2: tensor-core aggregation, cp.async double-buffered.
// C[64 j][128 p] = adj[j][:] @ (mwh + mwl), fused pos/neg + epilogue.
// Grid (8 j-tiles, 32 b) x 256 threads (8 warps: 2M x 4N).
// smem (floats): As 2x[64][36] | Bh 2x[32][132] | Bl 2x[32][132] | consts
//   AS=0 (2304/buf)  BH=4608 (4224/buf)  BL=13056  W1S=21504 VPS=21632
//   VNS=21760 CBS=21888 PNB=22016 POSS=22528 NEGS=22592  total 22656 fl (88.5KB)
// ---------------------------------------------------------------------------
#define AS_OFF  0
#define AS_BUF  2304
#define BH_OFF  4608
#define BB_BUF  4224
#define BL_OFF  13056
#define W1S_OFF 21504
#define VPS_OFF 21632
#define VNS_OFF 21760
#define CBS_OFF 21888
#define PNB_OFF 22016
#define POS_OFF 22528
#define NEG_OFF 22592
#define SMF_TOT 22656

__global__ __launch_bounds__(256, 2) void agg_mma_kernel(
    const float* __restrict__ adj, const float* __restrict__ weight,
    const float* __restrict__ x, const float* __restrict__ W1,
    float* __restrict__ out) {
    extern __shared__ float sm[];
    uint32_t smu = (uint32_t)__cvta_generic_to_shared(sm);

    int tid = threadIdx.x;
    int warp = tid >> 5;
    int lane = tid & 31;
    int warpM = warp >> 2;            // 0..1
    int warpN = warp & 3;             // 0..3
    int g4 = lane >> 2;               // 0..7
    int t4 = lane & 3;                // 0..3
    int b = blockIdx.y;
    int j0 = blockIdx.x * 64;

    if (tid < 128) {
        sm[W1S_OFF + tid] = W1[tid];
        sm[VPS_OFF + tid] = g_vp[tid];
        sm[VNS_OFF + tid] = g_vn[tid];
        sm[CBS_OFF + tid] = g_cb[tid];
    }

    const float* adj_b = adj + (size_t)b * Nn * Nn;
    const float* w_b   = weight + (size_t)b * Nn * Nn;
    const float* mwh_b = g_mwh + (size_t)b * Nn * Pn;
    const float* mwl_b = g_mwl + (size_t)b * Nn * Pn;

    int jj = tid & 63;                // pos/neg column
    int ks = tid >> 6;                // 0..3 k-subgroup

    float C[2][4][4];
    #pragma unroll
    for (int mt = 0; mt < 2; ++mt)
        #pragma unroll
        for (int nt = 0; nt < 4; ++nt)
            #pragma unroll
            for (int c = 0; c < 4; ++c) C[mt][nt][c] = 0.f;
    float posr = 0.f, negr = 0.f;

    // ---- staging (cp.async, 10 x 16B per thread) ----
    auto stage = [&](int chunk, int buf) {
        int k0 = chunk * 32;
        uint32_t asb = smu + (AS_OFF + buf * AS_BUF) * 4;
        #pragma unroll
        for (int s = 0; s < 2; ++s) {
            int idx = tid + s * 256;           // 0..511
            int row = idx >> 3;
            int q = idx & 7;
            cpasync16(asb + (row * 36 + q * 4) * 4,
                      &adj_b[(size_t)(j0 + row) * Nn + k0 + q * 4]);
        }
        uint32_t bhb = smu + (BH_OFF + buf * BB_BUF) * 4;
        uint32_t blb = smu + (BL_OFF + buf * BB_BUF) * 4;
        #pragma unroll
        for (int s = 0; s < 4; ++s) {
            int idx = tid + s * 256;           // 0..1023
            int k = idx >> 5;
            int p4 = (idx & 31) << 2;
            cpasync16(bhb + (k * 132 + p4) * 4, &mwh_b[(k0 + k) * Pn + p4]);
            cpasync16(blb + (k * 132 + p4) * 4, &mwl_b[(k0 + k) * Pn + p4]);
        }
    };

    stage(0, 0);
    cpasync_commit();

    for (int chunk = 0; chunk < 16; ++chunk) {
        int cur = chunk & 1;
        int k0 = chunk * 32;

        if (chunk < 15) {
            stage(chunk + 1, cur ^ 1);
            cpasync_commit();
            asm volatile("cp.async.wait_group 1;");
        } else {
            asm volatile("cp.async.wait_group 0;");
        }
        __syncthreads();

        const float* As_ = sm + AS_OFF + cur * AS_BUF;
        const float* Bh_ = sm + BH_OFF + cur * BB_BUF;
        const float* Bl_ = sm + BL_OFF + cur * BB_BUF;

        // prefetch weight rows for pos/neg (independent LDGs)
        float wv[8];
        #pragma unroll
        for (int s = 0; s < 8; ++s)
            wv[s] = w_b[(size_t)(k0 + ks * 8 + s) * Nn + j0 + jj];

        // MMA mainloop: 4 k8 steps
        #pragma unroll
        for (int kk = 0; kk < 4; ++kk) {
            int kb = kk * 8;
            uint32_t afr[2][4];
            #pragma unroll
            for (int mt = 0; mt < 2; ++mt) {
                int r = warpM * 32 + mt * 16 + g4;
                int c = kb + t4;
                afr[mt][0] = __float_as_uint(As_[r * 36 + c]);
                afr[mt][1] = __float_as_uint(As_[(r + 8) * 36 + c]);
                afr[mt][2] = __float_as_uint(As_[r * 36 + c + 4]);
                afr[mt][3] = __float_as_uint(As_[(r + 8) * 36 + c + 4]);
            }
            #pragma unroll
            for (int nt = 0; nt < 4; ++nt) {
                int p = warpN * 32 + nt * 8 + g4;
                uint32_t bh0 = __float_as_uint(Bh_[(kb + t4) * 132 + p]);
                uint32_t bh1 = __float_as_uint(Bh_[(kb + t4 + 4) * 132 + p]);
                uint32_t bl0 = __float_as_uint(Bl_[(kb + t4) * 132 + p]);
                uint32_t bl1 = __float_as_uint(Bl_[(kb + t4 + 4) * 132 + p]);
                #pragma unroll
                for (int mt = 0; mt < 2; ++mt) {
                    mma_tf32(C[mt][nt], afr[mt], bh0, bh1);
                    mma_tf32(C[mt][nt], afr[mt], bl0, bl1);
                }
            }
        }

        // pos/neg accumulation (adj mask from staged A tile; exactly 0/1)
        #pragma unroll
        for (int s = 0; s < 8; ++s) {
            float a = As_[jj * 36 + ks * 8 + s];
            posr += a * fmaxf(wv[s], 0.f);
            negr += a * fmaxf(-wv[s], 0.f);
        }
        __syncthreads();   // done reading buf cur (restaged at chunk+2)
    }

    // pos/neg reduction (deterministic order)
    sm[PNB_OFF + ks * 64 + jj]       = posr;
    sm[PNB_OFF + 256 + ks * 64 + jj] = negr;
    __syncthreads();
    if (tid < 64) {
        const float* p = sm + PNB_OFF;
        sm[POS_OFF + tid] = (p[tid] + p[64 + tid]) + (p[128 + tid] + p[192 + tid]);
    } else if (tid < 128) {
        int j = tid - 64;
        const float* p = sm + PNB_OFF + 256;
        sm[NEG_OFF + j] = (p[j] + p[64 + j]) + (p[128 + j] + p[192 + j]);
    }
    __syncthreads();

    // Epilogue: out = relu(x*W1 + C + pos*vp + neg*vn + cb)
    const float* W1s  = sm + W1S_OFF;
    const float* vps  = sm + VPS_OFF;
    const float* vns  = sm + VNS_OFF;
    const float* cbs  = sm + CBS_OFF;
    #pragma unroll
    for (int mt = 0; mt < 2; ++mt) {
        #pragma unroll
        for (int half = 0; half < 2; ++half) {
            int j = warpM * 32 + mt * 16 + g4 + half * 8;
            int gj = j0 + j;
            float xv = x[b * Nn + gj];
            float pj = sm[POS_OFF + j];
            float nj = sm[NEG_OFF + j];
            #pragma unroll
            for (int nt = 0; nt < 4; ++nt) {
                int p = warpN * 32 + nt * 8 + 2 * t4;
                float c0 = C[mt][nt][half * 2 + 0];
                float c1 = C[mt][nt][half * 2 + 1];
                float2 o;
                o.x = fmaxf(xv * W1s[p] + c0 + pj * vps[p] + nj * vns[p] + cbs[p], 0.f);
                o.y = fmaxf(xv * W1s[p + 1] + c1 + pj * vps[p + 1] + nj * vns[p + 1] + cbs[p + 1], 0.f);
                *(float2*)&out[((size_t)b * Nn + gj) * Pn + p] = o;
            }
        }
    }
}

// ---------------------------------------------------------------------------
extern "C" void kernel_launch(void* const* d_in, const int* in_sizes, int n_in,
                              void* d_out, int out_size) {
    const float* x      = (const float*)d_in[0];
    const float* mu     = (const float*)d_in[1];
    const float* weight = (const float*)d_in[2];
    const float* adj    = (const float*)d_in[3];
    const float* W1     = (const float*)d_in[4];
    const float* b1     = (const float*)d_in[5];
    const float* W2     = (const float*)d_in[6];
    const float* b2     = (const float*)d_in[7];
    const float* W3     = (const float*)d_in[8];
    const float* b3     = (const float*)d_in[9];
    const float* theta4 = (const float*)d_in[10];
    float* out = (float*)d_out;

    const int smem_bytes = SMF_TOT * 4;   // 90624 B
    static int configured = -1;
    if (configured < 0) {
        cudaFuncSetAttribute(agg_mma_kernel,
                             cudaFuncAttributeMaxDynamicSharedMemorySize,
                             smem_bytes);
        configured = 1;
    }

    mw_kernel<<<Bn * Nn / 64 + 1, 256>>>(mu, W2, W3, theta4, b1, b2, b3);
    dim3 grid(Nn / 64, Bn);
    agg_mma_kernel<<<grid, 256, smem_bytes>>>(adj, weight, x, W1, out);
}

// round 12
// speedup vs baseline: 2.1390x; 1.2931x over previous
#include <cuda_runtime.h>
#include <stdint.h>

#define Bn 32
#define Nn 512
#define Pn 128

// Scratch (static device globals: allocation-free)
__device__ uint32_t g_mwhP[Bn * (Nn / 2) * Pn];  // bf16x2 hi pairs (4 MB)
__device__ uint32_t g_mwlP[Bn * (Nn / 2) * Pn];  // bf16x2 lo pairs (4 MB)
__device__ float g_vp[Pn];
__device__ float g_vn[Pn];
__device__ float g_cb[Pn];                        // b1 + b2 + b3

// ---- packed f32x2 helpers (PTX-only packed-FP32 pipe) ---------------------
__device__ __forceinline__ void fma2(unsigned long long& d,
                                     unsigned long long a,
                                     unsigned long long b) {
    asm("fma.rn.f32x2 %0, %1, %2, %3;" : "=l"(d) : "l"(a), "l"(b), "l"(d));
}
__device__ __forceinline__ unsigned long long rep2(float a) {
    unsigned long long p;
    asm("mov.b64 %0, {%1, %1};" : "=l"(p) : "f"(a));
    return p;
}
__device__ __forceinline__ float2 unpack2(unsigned long long p) {
    float2 r;
    asm("mov.b64 {%0, %1}, %2;" : "=f"(r.x), "=f"(r.y) : "l"(p));
    return r;
}
// pack two f32 into bf16x2: result = {hi: a, lo: b}
__device__ __forceinline__ uint32_t pack_bf16x2(float hi, float lo) {
    uint32_t d;
    asm("cvt.rn.bf16x2.f32 %0, %1, %2;" : "=r"(d) : "f"(hi), "f"(lo));
    return d;
}

// ---- bf16 mma m16n8k16: D(fp32) += A(bf16) @ B(bf16) ----------------------
__device__ __forceinline__ void mma_bf16(float* c, const uint32_t* a,
                                         uint32_t b0, uint32_t b1) {
    asm volatile(
        "mma.sync.aligned.m16n8k16.row.col.f32.bf16.bf16.f32 "
        "{%0,%1,%2,%3}, {%4,%5,%6,%7}, {%8,%9}, {%0,%1,%2,%3};"
        : "+f"(c[0]), "+f"(c[1]), "+f"(c[2]), "+f"(c[3])
        : "r"(a[0]), "r"(a[1]), "r"(a[2]), "r"(a[3]), "r"(b0), "r"(b1));
}

// ---- cp.async 16B ---------------------------------------------------------
__device__ __forceinline__ void cpasync16(uint32_t dst, const void* src) {
    asm volatile("cp.async.cg.shared.global [%0], [%1], 16;"
                 :: "r"(dst), "l"(src));
}
__device__ __forceinline__ void cpasync_commit() {
    asm volatile("cp.async.commit_group;");
}

// ---------------------------------------------------------------------------
// Phase 1: mu @ W2 (f32x2 GEMM, validated). Epilogue emits k-pair-packed
// bf16x2 hi/lo (rows ty*4+u are consecutive -> local pairing, no smem bounce).
// Last CTA: prep.
// ---------------------------------------------------------------------------
__global__ __launch_bounds__(256) void mw_kernel(const float* __restrict__ mu,
                                                 const float* __restrict__ W2,
                                                 const float* __restrict__ W3,
                                                 const float* __restrict__ theta4,
                                                 const float* __restrict__ b1,
                                                 const float* __restrict__ b2,
                                                 const float* __restrict__ b3) {
    if (blockIdx.x == gridDim.x - 1) {
        int p = threadIdx.x;
        if (p < Pn) {
            float vp = 0.f, vn = 0.f;
            #pragma unroll 8
            for (int q = 0; q < Pn; ++q) {
                float t = theta4[q];
                float w = W3[q * Pn + p];
                vp += fmaxf(t, 0.f) * w;
                vn += fmaxf(-t, 0.f) * w;
            }
            g_vp[p] = vp;
            g_vn[p] = vn;
            g_cb[p] = b1[p] + b2[p] + b3[p];
        }
        return;
    }

    __shared__ float As[32 * 68];
    __shared__ float Bs[32 * 128];

    int tid = threadIdx.x;
    int tx = tid & 15;
    int ty = tid >> 4;
    int r0 = blockIdx.x * 64;

    unsigned long long acc2[4][4];
    #pragma unroll
    for (int u = 0; u < 4; ++u)
        #pragma unroll
        for (int q = 0; q < 4; ++q) acc2[u][q] = 0ull;

    for (int kb = 0; kb < 4; ++kb) {
        int k0 = kb * 32;
        #pragma unroll
        for (int s = 0; s < 2; ++s) {
            int idx = tid + s * 256;
            int m = idx >> 3;
            int kq = idx & 7;
            float4 f = *(const float4*)&mu[(r0 + m) * Pn + k0 + kq * 4];
            As[(kq * 4 + 0) * 68 + m] = f.x;
            As[(kq * 4 + 1) * 68 + m] = f.y;
            As[(kq * 4 + 2) * 68 + m] = f.z;
            As[(kq * 4 + 3) * 68 + m] = f.w;
        }
        #pragma unroll
        for (int s = 0; s < 4; ++s) {
            int idx = tid + s * 256;
            int k = idx >> 5;
            int c = idx & 31;
            *(float4*)&Bs[k * 128 + c * 4] =
                *(const float4*)&W2[(k0 + k) * Pn + c * 4];
        }
        __syncthreads();

        #pragma unroll
        for (int k = 0; k < 32; ++k) {
            float4 a4 = *(const float4*)&As[k * 68 + ty * 4];
            ulonglong2 B0 = *(const ulonglong2*)&Bs[k * 128 + tx * 8];
            ulonglong2 B1 = *(const ulonglong2*)&Bs[k * 128 + tx * 8 + 4];
            unsigned long long pa[4] = {rep2(a4.x), rep2(a4.y), rep2(a4.z), rep2(a4.w)};
            #pragma unroll
            for (int u = 0; u < 4; ++u) {
                fma2(acc2[u][0], pa[u], B0.x);
                fma2(acc2[u][1], pa[u], B0.y);
                fma2(acc2[u][2], pa[u], B1.x);
                fma2(acc2[u][3], pa[u], B1.y);
            }
        }
        __syncthreads();
    }

    // Epilogue: rows (u, u+1) pair -> bf16x2 {lo: row even, hi: row odd}
    float v[4][8];
    #pragma unroll
    for (int u = 0; u < 4; ++u)
        #pragma unroll
        for (int q = 0; q < 4; ++q) {
            float2 t = unpack2(acc2[u][q]);
            v[u][q * 2] = t.x;
            v[u][q * 2 + 1] = t.y;
        }
    #pragma unroll
    for (int u = 0; u < 4; u += 2) {
        size_t ip = (size_t)(r0 + ty * 4 + u) >> 1;   // global pair index
        uint32_t hp[8], lp[8];
        #pragma unroll
        for (int q = 0; q < 8; ++q) {
            float v0 = v[u][q], v1 = v[u + 1][q];
            uint32_t h = pack_bf16x2(v1, v0);
            float h0 = __uint_as_float(h << 16);
            float h1 = __uint_as_float(h & 0xFFFF0000u);
            hp[q] = h;
            lp[q] = pack_bf16x2(v1 - h1, v0 - h0);
        }
        *(uint4*)&g_mwhP[ip * Pn + tx * 8]     = make_uint4(hp[0], hp[1], hp[2], hp[3]);
        *(uint4*)&g_mwhP[ip * Pn + tx * 8 + 4] = make_uint4(hp[4], hp[5], hp[6], hp[7]);
        *(uint4*)&g_mwlP[ip * Pn + tx * 8]     = make_uint4(lp[0], lp[1], lp[2], lp[3]);
        *(uint4*)&g_mwlP[ip * Pn + tx * 8 + 4] = make_uint4(lp[4], lp[5], lp[6], lp[7]);
    }
}

// ---------------------------------------------------------------------------
// Phase 2: bf16 tensor-core aggregation, cp.async double-buffered.
// C[64 j][128 p] = adj @ (mwh + mwl), fused pos/neg + epilogue.
// Grid (8 j-tiles, 32 b) x 256 threads (8 warps: 2M x 4N).
// smem(4B units): As 2x[64][36] | BhP 2x[16][136] | BlP 2x[16][136] | consts
// ---------------------------------------------------------------------------
#define AS_OFF  0
#define AS_BUF  2304
#define BH_OFF  4608
#define BB_BUF  2176
#define BL_OFF  8960
#define W1S_OFF 13312
#define VPS_OFF 13440
#define VNS_OFF 13568
#define CBS_OFF 13696
#define PNB_OFF 13824
#define POS_OFF 14336
#define NEG_OFF 14400
#define SMF_TOT 14464

__global__ __launch_bounds__(256, 2) void agg_mma_kernel(
    const float* __restrict__ adj, const float* __restrict__ weight,
    const float* __restrict__ x, const float* __restrict__ W1,
    float* __restrict__ out) {
    extern __shared__ float sm[];
    uint32_t smu = (uint32_t)__cvta_generic_to_shared(sm);

    int tid = threadIdx.x;
    int warp = tid >> 5;
    int lane = tid & 31;
    int warpM = warp >> 2;            // 0..1
    int warpN = warp & 3;             // 0..3
    int g4 = lane >> 2;               // 0..7
    int t4 = lane & 3;                // 0..3
    int b = blockIdx.y;
    int j0 = blockIdx.x * 64;

    if (tid < 128) {
        sm[W1S_OFF + tid] = W1[tid];
        sm[VPS_OFF + tid] = g_vp[tid];
        sm[VNS_OFF + tid] = g_vn[tid];
        sm[CBS_OFF + tid] = g_cb[tid];
    }

    const float* adj_b = adj + (size_t)b * Nn * Nn;
    const float* w_b   = weight + (size_t)b * Nn * Nn;
    const uint32_t* mwh_b = g_mwhP + (size_t)b * (Nn / 2) * Pn;
    const uint32_t* mwl_b = g_mwlP + (size_t)b * (Nn / 2) * Pn;

    int jj = tid & 63;                // pos/neg column
    int ks = tid >> 6;                // 0..3 k-subgroup

    float C[2][4][4];
    #pragma unroll
    for (int mt = 0; mt < 2; ++mt)
        #pragma unroll
        for (int nt = 0; nt < 4; ++nt)
            #pragma unroll
            for (int c = 0; c < 4; ++c) C[mt][nt][c] = 0.f;
    float posr = 0.f, negr = 0.f;

    // ---- staging (cp.async, 6 x 16B per thread) ----
    auto stage = [&](int chunk, int buf) {
        int k0 = chunk * 32;
        uint32_t asb = smu + (AS_OFF + buf * AS_BUF) * 4;
        #pragma unroll
        for (int s = 0; s < 2; ++s) {
            int idx = tid + s * 256;           // 0..511
            int row = idx >> 3;
            int q = idx & 7;
            cpasync16(asb + (row * 36 + q * 4) * 4,
                      &adj_b[(size_t)(j0 + row) * Nn + k0 + q * 4]);
        }
        uint32_t bhb = smu + (BH_OFF + buf * BB_BUF) * 4;
        uint32_t blb = smu + (BL_OFF + buf * BB_BUF) * 4;
        #pragma unroll
        for (int s = 0; s < 2; ++s) {
            int idx = tid + s * 256;           // 0..511
            int pr = idx >> 5;                 // pair-row 0..15
            int p4 = (idx & 31) << 2;
            cpasync16(bhb + (pr * 136 + p4) * 4,
                      &mwh_b[(size_t)(chunk * 16 + pr) * Pn + p4]);
            cpasync16(blb + (pr * 136 + p4) * 4,
                      &mwl_b[(size_t)(chunk * 16 + pr) * Pn + p4]);
        }
    };

    stage(0, 0);
    cpasync_commit();

    for (int chunk = 0; chunk < 16; ++chunk) {
        int cur = chunk & 1;
        int k0 = chunk * 32;

        if (chunk < 15) {
            stage(chunk + 1, cur ^ 1);
            cpasync_commit();
            asm volatile("cp.async.wait_group 1;");
        } else {
            asm volatile("cp.async.wait_group 0;");
        }
        __syncthreads();

        const float* As_ = sm + AS_OFF + cur * AS_BUF;
        const uint32_t* Bh_ = (const uint32_t*)(sm + BH_OFF + cur * BB_BUF);
        const uint32_t* Bl_ = (const uint32_t*)(sm + BL_OFF + cur * BB_BUF);

        // prefetch weight rows for pos/neg (independent LDGs)
        float wv[8];
        #pragma unroll
        for (int s = 0; s < 8; ++s)
            wv[s] = w_b[(size_t)(k0 + ks * 8 + s) * Nn + j0 + jj];

        // MMA mainloop: 2 k16 steps
        #pragma unroll
        for (int kk = 0; kk < 2; ++kk) {
            int kb = kk * 16;
            uint32_t afr[2][4];
            #pragma unroll
            for (int mt = 0; mt < 2; ++mt) {
                int r = warpM * 32 + mt * 16 + g4;
                int c = kb + 2 * t4;
                float2 f0 = *(const float2*)&As_[r * 36 + c];
                float2 f1 = *(const float2*)&As_[(r + 8) * 36 + c];
                float2 f2 = *(const float2*)&As_[r * 36 + c + 8];
                float2 f3 = *(const float2*)&As_[(r + 8) * 36 + c + 8];
                afr[mt][0] = pack_bf16x2(f0.y, f0.x);
                afr[mt][1] = pack_bf16x2(f1.y, f1.x);
                afr[mt][2] = pack_bf16x2(f2.y, f2.x);
                afr[mt][3] = pack_bf16x2(f3.y, f3.x);
            }
            int prb = kk * 8 + t4;             // pair-row base within chunk
            #pragma unroll
            for (int nt = 0; nt < 4; ++nt) {
                int p = warpN * 32 + nt * 8 + g4;
                uint32_t bh0 = Bh_[prb * 136 + p];
                uint32_t bh1 = Bh_[(prb + 4) * 136 + p];
                uint32_t bl0 = Bl_[prb * 136 + p];
                uint32_t bl1 = Bl_[(prb + 4) * 136 + p];
                #pragma unroll
                for (int mt = 0; mt < 2; ++mt) {
                    mma_bf16(C[mt][nt], afr[mt], bh0, bh1);
                    mma_bf16(C[mt][nt], afr[mt], bl0, bl1);
                }
            }
        }

        // pos/neg accumulation (adj mask from staged A tile; exactly 0/1)
        #pragma unroll
        for (int s = 0; s < 8; ++s) {
            float a = As_[jj * 36 + ks * 8 + s];
            posr += a * fmaxf(wv[s], 0.f);
            negr += a * fmaxf(-wv[s], 0.f);
        }
        __syncthreads();   // done reading buf cur (restaged at chunk+2)
    }

    // pos/neg reduction (deterministic order)
    sm[PNB_OFF + ks * 64 + jj]       = posr;
    sm[PNB_OFF + 256 + ks * 64 + jj] = negr;
    __syncthreads();
    if (tid < 64) {
        const float* p = sm + PNB_OFF;
        sm[POS_OFF + tid] = (p[tid] + p[64 + tid]) + (p[128 + tid] + p[192 + tid]);
    } else if (tid < 128) {
        int j = tid - 64;
        const float* p = sm + PNB_OFF + 256;
        sm[NEG_OFF + j] = (p[j] + p[64 + j]) + (p[128 + j] + p[192 + j]);
    }
    __syncthreads();

    // Epilogue: out = relu(x*W1 + C + pos*vp + neg*vn + cb)
    const float* W1s  = sm + W1S_OFF;
    const float* vps  = sm + VPS_OFF;
    const float* vns  = sm + VNS_OFF;
    const float* cbs  = sm + CBS_OFF;
    #pragma unroll
    for (int mt = 0; mt < 2; ++mt) {
        #pragma unroll
        for (int half = 0; half < 2; ++half) {
            int j = warpM * 32 + mt * 16 + g4 + half * 8;
            int gj = j0 + j;
            float xv = x[b * Nn + gj];
            float pj = sm[POS_OFF + j];
            float nj = sm[NEG_OFF + j];
            #pragma unroll
            for (int nt = 0; nt < 4; ++nt) {
                int p = warpN * 32 + nt * 8 + 2 * t4;
                float c0 = C[mt][nt][half * 2 + 0];
                float c1 = C[mt][nt][half * 2 + 1];
                float2 o;
                o.x = fmaxf(xv * W1s[p] + c0 + pj * vps[p] + nj * vns[p] + cbs[p], 0.f);
                o.y = fmaxf(xv * W1s[p + 1] + c1 + pj * vps[p + 1] + nj * vns[p + 1] + cbs[p + 1], 0.f);
                *(float2*)&out[((size_t)b * Nn + gj) * Pn + p] = o;
            }
        }
    }
}

// ---------------------------------------------------------------------------
extern "C" void kernel_launch(void* const* d_in, const int* in_sizes, int n_in,
                              void* d_out, int out_size) {
    const float* x      = (const float*)d_in[0];
    const float* mu     = (const float*)d_in[1];
    const float* weight = (const float*)d_in[2];
    const float* adj    = (const float*)d_in[3];
    const float* W1     = (const float*)d_in[4];
    const float* b1     = (const float*)d_in[5];
    const float* W2     = (const float*)d_in[6];
    const float* b2     = (const float*)d_in[7];
    const float* W3     = (const float*)d_in[8];
    const float* b3     = (const float*)d_in[9];
    const float* theta4 = (const float*)d_in[10];
    float* out = (float*)d_out;

    const int smem_bytes = SMF_TOT * 4;   // 57856 B
    static int configured = -1;
    if (configured < 0) {
        cudaFuncSetAttribute(agg_mma_kernel,
                             cudaFuncAttributeMaxDynamicSharedMemorySize,
                             smem_bytes);
        configured = 1;
    }

    mw_kernel<<<Bn * Nn / 64 + 1, 256>>>(mu, W2, W3, theta4, b1, b2, b3);
    dim3 grid(Nn / 64, Bn);
    agg_mma_kernel<<<grid, 256, smem_bytes>>>(adj, weight, x, W1, out);
}

// round 13
// speedup vs baseline: 2.7062x; 1.2652x over previous
#include <cuda_runtime.h>
#include <stdint.h>

#define Bn 32
#define Nn 512
#define Pn 128

// ---- helpers --------------------------------------------------------------
__device__ __forceinline__ uint32_t pack_bf16x2(float hi, float lo) {
    uint32_t d;
    asm("cvt.rn.bf16x2.f32 %0, %1, %2;" : "=r"(d) : "f"(hi), "f"(lo));
    return d;
}
__device__ __forceinline__ float bf_lo(uint32_t u) {
    return __uint_as_float(u << 16);
}
__device__ __forceinline__ float bf_hi(uint32_t u) {
    return __uint_as_float(u & 0xFFFF0000u);
}

// bf16 mma m16n8k16: D(fp32) += A(bf16) @ B(bf16)
__device__ __forceinline__ void mma_bf16(float* c, const uint32_t* a,
                                         uint32_t b0, uint32_t b1) {
    asm volatile(
        "mma.sync.aligned.m16n8k16.row.col.f32.bf16.bf16.f32 "
        "{%0,%1,%2,%3}, {%4,%5,%6,%7}, {%8,%9}, {%0,%1,%2,%3};"
        : "+f"(c[0]), "+f"(c[1]), "+f"(c[2]), "+f"(c[3])
        : "r"(a[0]), "r"(a[1]), "r"(a[2]), "r"(a[3]), "r"(b0), "r"(b1));
}

__device__ __forceinline__ void cpasync16(uint32_t dst, const void* src) {
    asm volatile("cp.async.cg.shared.global [%0], [%1], 16;"
                 :: "r"(dst), "l"(src));
}
__device__ __forceinline__ void cpasync_commit() {
    asm volatile("cp.async.commit_group;");
}

// ---------------------------------------------------------------------------
// Single fused kernel. Grid (8 j-tiles, 32 b) x 256 threads (8 warps: 2M x 4N).
//   S[64 j][128 k'] = adj @ mu        (bf16-split MMA, cp.async pipeline)
//   D = S @ W2                         (bf16 3-term split, 2 k-halves)
//   out = relu(x*W1 + D + pos*vp + neg*vn + cb)   (pos/neg fused in mainloop)
// vp/vn/cb computed per-CTA at start, overlapped with chunk-0 cp.async.
//
// smem (float units):
//   pipeline: As 2x[64][36]=4608 | Mu 2x[32][132]=8448  (dead after mainloop)
//   epilogue overlay: Sh [64][68]=4352 | Sl 4352 | W2s [64][132]=8448
//   consts at 17152+
// ---------------------------------------------------------------------------
#define AS_OFF  0
#define AS_BUF  2304
#define MU_OFF  4608
#define MU_BUF  4224
#define SH_OFF  0
#define SL_OFF  4352
#define W2S_OFF 8704
#define W1S_OFF 17152
#define VPS_OFF 17280
#define VNS_OFF 17408
#define CBS_OFF 17536
#define PNB_OFF 17664
#define POS_OFF 18176
#define NEG_OFF 18240
#define SMF_TOT 18304

__global__ __launch_bounds__(256, 2) void s2v_kernel(
    const float* __restrict__ adj, const float* __restrict__ weight,
    const float* __restrict__ mu, const float* __restrict__ x,
    const float* __restrict__ W1, const float* __restrict__ W2,
    const float* __restrict__ W3, const float* __restrict__ theta4,
    const float* __restrict__ b1, const float* __restrict__ b2,
    const float* __restrict__ b3, float* __restrict__ out) {
    extern __shared__ float sm[];
    uint32_t smu = (uint32_t)__cvta_generic_to_shared(sm);

    int tid = threadIdx.x;
    int warp = tid >> 5;
    int lane = tid & 31;
    int warpM = warp >> 2;            // 0..1
    int warpN = warp & 3;             // 0..3
    int g4 = lane >> 2;               // 0..7
    int t4 = lane & 3;                // 0..3
    int b = blockIdx.y;
    int j0 = blockIdx.x * 64;

    const float* adj_b = adj + (size_t)b * Nn * Nn;
    const float* w_b   = weight + (size_t)b * Nn * Nn;
    const float* mu_b  = mu + (size_t)b * Nn * Pn;

    int jj = tid & 63;                // pos/neg column
    int ks = tid >> 6;                // 0..3 k-subgroup

    // ---- staging (cp.async, 6 x 16B per thread) ----
    auto stage = [&](int chunk, int buf) {
        int k0 = chunk * 32;
        uint32_t asb = smu + (AS_OFF + buf * AS_BUF) * 4;
        #pragma unroll
        for (int s = 0; s < 2; ++s) {
            int idx = tid + s * 256;           // 0..511
            int row = idx >> 3;
            int q = idx & 7;
            cpasync16(asb + (row * 36 + q * 4) * 4,
                      &adj_b[(size_t)(j0 + row) * Nn + k0 + q * 4]);
        }
        uint32_t mub = smu + (MU_OFF + buf * MU_BUF) * 4;
        #pragma unroll
        for (int s = 0; s < 4; ++s) {
            int idx = tid + s * 256;           // 0..1023
            int k = idx >> 5;
            int c = idx & 31;
            cpasync16(mub + (k * 132 + c * 4) * 4,
                      &mu_b[(size_t)(k0 + k) * Pn + c * 4]);
        }
    };

    stage(0, 0);
    cpasync_commit();

    // ---- prep (overlapped with chunk-0 fill): vp/vn/cb/W1 ----
    if (tid < 128) {
        int p = tid;
        float vp = 0.f, vn = 0.f;
        #pragma unroll 8
        for (int q = 0; q < Pn; ++q) {
            float t = theta4[q];
            float w = W3[q * Pn + p];
            vp += fmaxf(t, 0.f) * w;
            vn += fmaxf(-t, 0.f) * w;
        }
        sm[VPS_OFF + p] = vp;
        sm[VNS_OFF + p] = vn;
        sm[CBS_OFF + p] = b1[p] + b2[p] + b3[p];
        sm[W1S_OFF + p] = W1[p];
    }

    float C[2][4][4];
    #pragma unroll
    for (int mt = 0; mt < 2; ++mt)
        #pragma unroll
        for (int nt = 0; nt < 4; ++nt)
            #pragma unroll
            for (int c = 0; c < 4; ++c) C[mt][nt][c] = 0.f;
    float posr = 0.f, negr = 0.f;

    // ================= mainloop: S = adj @ mu =================
    for (int chunk = 0; chunk < 16; ++chunk) {
        int cur = chunk & 1;
        int k0 = chunk * 32;

        if (chunk < 15) {
            stage(chunk + 1, cur ^ 1);
            cpasync_commit();
            asm volatile("cp.async.wait_group 1;");
        } else {
            asm volatile("cp.async.wait_group 0;");
        }
        __syncthreads();

        const float* As_ = sm + AS_OFF + cur * AS_BUF;
        const float* Mu_ = sm + MU_OFF + cur * MU_BUF;

        // prefetch weight rows for pos/neg (independent LDGs)
        float wv[8];
        #pragma unroll
        for (int s = 0; s < 8; ++s)
            wv[s] = w_b[(size_t)(k0 + ks * 8 + s) * Nn + j0 + jj];

        #pragma unroll
        for (int kk = 0; kk < 2; ++kk) {
            int kb = kk * 16;
            uint32_t afr[2][4];
            #pragma unroll
            for (int mt = 0; mt < 2; ++mt) {
                int r = warpM * 32 + mt * 16 + g4;
                int c = kb + 2 * t4;
                float2 f0 = *(const float2*)&As_[r * 36 + c];
                float2 f1 = *(const float2*)&As_[(r + 8) * 36 + c];
                float2 f2 = *(const float2*)&As_[r * 36 + c + 8];
                float2 f3 = *(const float2*)&As_[(r + 8) * 36 + c + 8];
                afr[mt][0] = pack_bf16x2(f0.y, f0.x);   // adj exact in bf16
                afr[mt][1] = pack_bf16x2(f1.y, f1.x);
                afr[mt][2] = pack_bf16x2(f2.y, f2.x);
                afr[mt][3] = pack_bf16x2(f3.y, f3.x);
            }
            #pragma unroll
            for (int nt = 0; nt < 4; ++nt) {
                int p = warpN * 32 + nt * 8 + g4;
                float m0 = Mu_[(kb + 2 * t4) * 132 + p];
                float m1 = Mu_[(kb + 2 * t4 + 1) * 132 + p];
                float m2 = Mu_[(kb + 2 * t4 + 8) * 132 + p];
                float m3 = Mu_[(kb + 2 * t4 + 9) * 132 + p];
                uint32_t bh0 = pack_bf16x2(m1, m0);
                uint32_t bh1 = pack_bf16x2(m3, m2);
                uint32_t bl0 = pack_bf16x2(m1 - bf_hi(bh0), m0 - bf_lo(bh0));
                uint32_t bl1 = pack_bf16x2(m3 - bf_hi(bh1), m2 - bf_lo(bh1));
                #pragma unroll
                for (int mt = 0; mt < 2; ++mt) {
                    mma_bf16(C[mt][nt], afr[mt], bh0, bh1);
                    mma_bf16(C[mt][nt], afr[mt], bl0, bl1);
                }
            }
        }

        // pos/neg accumulation (adj mask from staged A tile; exactly 0/1)
        #pragma unroll
        for (int s = 0; s < 8; ++s) {
            float a = As_[jj * 36 + ks * 8 + s];
            posr += a * fmaxf(wv[s], 0.f);
            negr += a * fmaxf(-wv[s], 0.f);
        }
        __syncthreads();   // done reading buf cur (restaged at chunk+2)
    }

    // ================= pack S -> smem (bf16 hi/lo, k-pair layout) ==========
    __syncthreads();   // pipeline buffers globally dead
    #pragma unroll
    for (int mt = 0; mt < 2; ++mt) {
        int rb = warpM * 32 + mt * 16;
        #pragma unroll
        for (int nt = 0; nt < 4; ++nt) {
            int kp = warpN * 16 + nt * 4 + t4;
            float c0 = C[mt][nt][0], c1 = C[mt][nt][1];   // row rb+g4
            float c2 = C[mt][nt][2], c3 = C[mt][nt][3];   // row rb+g4+8
            uint32_t h0 = pack_bf16x2(c1, c0);
            uint32_t l0 = pack_bf16x2(c1 - bf_hi(h0), c0 - bf_lo(h0));
            uint32_t h1 = pack_bf16x2(c3, c2);
            uint32_t l1 = pack_bf16x2(c3 - bf_hi(h1), c2 - bf_lo(h1));
            sm[SH_OFF + (rb + g4) * 68 + kp]     = __uint_as_float(h0);
            sm[SL_OFF + (rb + g4) * 68 + kp]     = __uint_as_float(l0);
            sm[SH_OFF + (rb + g4 + 8) * 68 + kp] = __uint_as_float(h1);
            sm[SL_OFF + (rb + g4 + 8) * 68 + kp] = __uint_as_float(l1);
        }
    }

    // ================= D = S @ W2 (two 64-k halves, 3-term split) ==========
    float D[2][4][4];
    #pragma unroll
    for (int mt = 0; mt < 2; ++mt)
        #pragma unroll
        for (int nt = 0; nt < 4; ++nt)
            #pragma unroll
            for (int c = 0; c < 4; ++c) D[mt][nt][c] = 0.f;

    for (int h = 0; h < 2; ++h) {
        __syncthreads();   // S writes done / prev half's W2s reads done
        #pragma unroll
        for (int s = 0; s < 8; ++s) {
            int idx = tid + s * 256;           // 0..2047 float4s
            int k = idx >> 5;
            int c = idx & 31;
            *(float4*)&sm[W2S_OFF + k * 132 + c * 4] =
                *(const float4*)&W2[(size_t)(h * 64 + k) * Pn + c * 4];
        }
        __syncthreads();

        #pragma unroll
        for (int kk2 = 0; kk2 < 4; ++kk2) {
            uint32_t ah[2][4], al[2][4];
            #pragma unroll
            for (int mt = 0; mt < 2; ++mt) {
                int r = warpM * 32 + mt * 16 + g4;
                int base = h * 32 + kk2 * 8 + t4;
                ah[mt][0] = __float_as_uint(sm[SH_OFF + r * 68 + base]);
                ah[mt][1] = __float_as_uint(sm[SH_OFF + (r + 8) * 68 + base]);
                ah[mt][2] = __float_as_uint(sm[SH_OFF + r * 68 + base + 4]);
                ah[mt][3] = __float_as_uint(sm[SH_OFF + (r + 8) * 68 + base + 4]);
                al[mt][0] = __float_as_uint(sm[SL_OFF + r * 68 + base]);
                al[mt][1] = __float_as_uint(sm[SL_OFF + (r + 8) * 68 + base]);
                al[mt][2] = __float_as_uint(sm[SL_OFF + r * 68 + base + 4]);
                al[mt][3] = __float_as_uint(sm[SL_OFF + (r + 8) * 68 + base + 4]);
            }
            #pragma unroll
            for (int nt = 0; nt < 4; ++nt) {
                int p = warpN * 32 + nt * 8 + g4;
                int kl = kk2 * 16 + 2 * t4;
                float w0 = sm[W2S_OFF + kl * 132 + p];
                float w1 = sm[W2S_OFF + (kl + 1) * 132 + p];
                float w2 = sm[W2S_OFF + (kl + 8) * 132 + p];
                float w3 = sm[W2S_OFF + (kl + 9) * 132 + p];
                uint32_t bh0 = pack_bf16x2(w1, w0);
                uint32_t bh1 = pack_bf16x2(w3, w2);
                uint32_t bl0 = pack_bf16x2(w1 - bf_hi(bh0), w0 - bf_lo(bh0));
                uint32_t bl1 = pack_bf16x2(w3 - bf_hi(bh1), w2 - bf_lo(bh1));
                #pragma unroll
                for (int mt = 0; mt < 2; ++mt) {
                    mma_bf16(D[mt][nt], ah[mt], bh0, bh1);
                    mma_bf16(D[mt][nt], ah[mt], bl0, bl1);
                    mma_bf16(D[mt][nt], al[mt], bh0, bh1);
                }
            }
        }
    }

    // ================= pos/neg reduction (deterministic) ===================
    __syncthreads();
    sm[PNB_OFF + ks * 64 + jj]       = posr;
    sm[PNB_OFF + 256 + ks * 64 + jj] = negr;
    __syncthreads();
    if (tid < 64) {
        const float* p = sm + PNB_OFF;
        sm[POS_OFF + tid] = (p[tid] + p[64 + tid]) + (p[128 + tid] + p[192 + tid]);
    } else if (tid < 128) {
        int j = tid - 64;
        const float* p = sm + PNB_OFF + 256;
        sm[NEG_OFF + j] = (p[j] + p[64 + j]) + (p[128 + j] + p[192 + j]);
    }
    __syncthreads();

    // ================= final epilogue ======================================
    const float* W1s = sm + W1S_OFF;
    const float* vps = sm + VPS_OFF;
    const float* vns = sm + VNS_OFF;
    const float* cbs = sm + CBS_OFF;
    #pragma unroll
    for (int mt = 0; mt < 2; ++mt) {
        #pragma unroll
        for (int half = 0; half < 2; ++half) {
            int j = warpM * 32 + mt * 16 + g4 + half * 8;
            int gj = j0 + j;
            float xv = x[b * Nn + gj];
            float pj = sm[POS_OFF + j];
            float nj = sm[NEG_OFF + j];
            #pragma unroll
            for (int nt = 0; nt < 4; ++nt) {
                int p = warpN * 32 + nt * 8 + 2 * t4;
                float c0 = D[mt][nt][half * 2 + 0];
                float c1 = D[mt][nt][half * 2 + 1];
                float2 o;
                o.x = fmaxf(xv * W1s[p] + c0 + pj * vps[p] + nj * vns[p] + cbs[p], 0.f);
                o.y = fmaxf(xv * W1s[p + 1] + c1 + pj * vps[p + 1] + nj * vns[p + 1] + cbs[p + 1], 0.f);
                *(float2*)&out[((size_t)b * Nn + gj) * Pn + p] = o;
            }
        }
    }
}

// ---------------------------------------------------------------------------
extern "C" void kernel_launch(void* const* d_in, const int* in_sizes, int n_in,
                              void* d_out, int out_size) {
    const float* x      = (const float*)d_in[0];
    const float* mu     = (const float*)d_in[1];
    const float* weight = (const float*)d_in[2];
    const float* adj    = (const float*)d_in[3];
    const float* W1     = (const float*)d_in[4];
    const float* b1     = (const float*)d_in[5];
    const float* W2     = (const float*)d_in[6];
    const float* b2     = (const float*)d_in[7];
    const float* W3     = (const float*)d_in[8];
    const float* b3     = (const float*)d_in[9];
    const float* theta4 = (const float*)d_in[10];
    float* out = (float*)d_out;

    const int smem_bytes = SMF_TOT * 4;   // 73216 B
    static int configured = -1;
    if (configured < 0) {
        cudaFuncSetAttribute(s2v_kernel,
                             cudaFuncAttributeMaxDynamicSharedMemorySize,
                             smem_bytes);
        configured = 1;
    }

    dim3 grid(Nn / 64, Bn);
    s2v_kernel<<<grid, 256, smem_bytes>>>(adj, weight, mu, x, W1, W2, W3,
                                          theta4, b1, b2, b3, out);
}

// round 14
// speedup vs baseline: 2.8706x; 1.0607x over previous
#include <cuda_runtime.h>
#include <stdint.h>

#define Bn 32
#define Nn 512
#define Pn 128

// ---- helpers --------------------------------------------------------------
__device__ __forceinline__ uint32_t pack_bf16x2(float hi, float lo) {
    uint32_t d;
    asm("cvt.rn.bf16x2.f32 %0, %1, %2;" : "=r"(d) : "f"(hi), "f"(lo));
    return d;
}
__device__ __forceinline__ float bf_lo(uint32_t u) {
    return __uint_as_float(u << 16);
}
__device__ __forceinline__ float bf_hi(uint32_t u) {
    return __uint_as_float(u & 0xFFFF0000u);
}

// bf16 mma m16n8k16: D(fp32) += A(bf16) @ B(bf16)
__device__ __forceinline__ void mma_bf16(float* c, const uint32_t* a,
                                         uint32_t b0, uint32_t b1) {
    asm volatile(
        "mma.sync.aligned.m16n8k16.row.col.f32.bf16.bf16.f32 "
        "{%0,%1,%2,%3}, {%4,%5,%6,%7}, {%8,%9}, {%0,%1,%2,%3};"
        : "+f"(c[0]), "+f"(c[1]), "+f"(c[2]), "+f"(c[3])
        : "r"(a[0]), "r"(a[1]), "r"(a[2]), "r"(a[3]), "r"(b0), "r"(b1));
}

__device__ __forceinline__ void cpasync16(uint32_t dst, const void* src) {
    asm volatile("cp.async.cg.shared.global [%0], [%1], 16;"
                 :: "r"(dst), "l"(src));
}
__device__ __forceinline__ void cpasync_commit() {
    asm volatile("cp.async.commit_group;");
}

// ---------------------------------------------------------------------------
// Single fused kernel. Grid (8 j-tiles, 32 b) x 256 threads (8 warps: 2M x 4N).
//   S[64 j][128 k'] = adj @ mu   (bf16-split MMA, 64-k chunks, 1 sync/iter)
//   D = S @ W2                   (bf16 3-term split, 2 k-halves)
//   out = relu(x*W1 + D + pos*vp + neg*vn + cb)
// vp/vn/cb computed per-CTA at start, overlapped with chunk-0 cp.async.
//
// smem (float units), ~107 KB -> 2 CTA/SM:
//   pipeline: As 2x[64][68]=8704 | Mu 2x[64][132]=16896  (dead after mainloop)
//   epilogue overlay: Sh [64][68] | Sl [64][68] | W2s [64][132]
// ---------------------------------------------------------------------------
#define AS_OFF  0
#define AS_BUF  4352
#define MU_OFF  8704
#define MU_BUF  8448
#define SH_OFF  0
#define SL_OFF  4352
#define W2S_OFF 8704
#define W1S_OFF 25600
#define VPS_OFF 25728
#define VNS_OFF 25856
#define CBS_OFF 25984
#define PNB_OFF 26112
#define POS_OFF 26624
#define NEG_OFF 26688
#define SMF_TOT 26752

__global__ __launch_bounds__(256, 2) void s2v_kernel(
    const float* __restrict__ adj, const float* __restrict__ weight,
    const float* __restrict__ mu, const float* __restrict__ x,
    const float* __restrict__ W1, const float* __restrict__ W2,
    const float* __restrict__ W3, const float* __restrict__ theta4,
    const float* __restrict__ b1, const float* __restrict__ b2,
    const float* __restrict__ b3, float* __restrict__ out) {
    extern __shared__ float sm[];
    uint32_t smu = (uint32_t)__cvta_generic_to_shared(sm);

    int tid = threadIdx.x;
    int warp = tid >> 5;
    int lane = tid & 31;
    int warpM = warp >> 2;            // 0..1
    int warpN = warp & 3;             // 0..3
    int g4 = lane >> 2;               // 0..7
    int t4 = lane & 3;                // 0..3
    int b = blockIdx.y;
    int j0 = blockIdx.x * 64;

    const float* adj_b = adj + (size_t)b * Nn * Nn;
    const float* w_b   = weight + (size_t)b * Nn * Nn;
    const float* mu_b  = mu + (size_t)b * Nn * Pn;

    int jj = tid & 63;                // pos/neg column
    int ks = tid >> 6;                // 0..3 -> k-subrange ks*16..+15

    // ---- staging: one 64-k chunk (12 x 16B cp.async per thread) ----
    auto stage = [&](int chunk, int buf) {
        int k0 = chunk * 64;
        uint32_t asb = smu + (AS_OFF + buf * AS_BUF) * 4;
        #pragma unroll
        for (int s = 0; s < 4; ++s) {
            int idx = tid + s * 256;           // 0..1023
            int row = idx >> 4;
            int q = idx & 15;
            cpasync16(asb + (row * 68 + q * 4) * 4,
                      &adj_b[(size_t)(j0 + row) * Nn + k0 + q * 4]);
        }
        uint32_t mub = smu + (MU_OFF + buf * MU_BUF) * 4;
        #pragma unroll
        for (int s = 0; s < 8; ++s) {
            int idx = tid + s * 256;           // 0..2047
            int k = idx >> 5;
            int c = idx & 31;
            cpasync16(mub + (k * 132 + c * 4) * 4,
                      &mu_b[(size_t)(k0 + k) * Pn + c * 4]);
        }
    };

    stage(0, 0);
    cpasync_commit();

    // ---- prep (overlapped with chunk-0 fill): vp/vn/cb/W1 ----
    if (tid < 128) {
        int p = tid;
        float vp = 0.f, vn = 0.f;
        #pragma unroll 8
        for (int q = 0; q < Pn; ++q) {
            float t = theta4[q];
            float w = W3[q * Pn + p];
            vp += fmaxf(t, 0.f) * w;
            vn += fmaxf(-t, 0.f) * w;
        }
        sm[VPS_OFF + p] = vp;
        sm[VNS_OFF + p] = vn;
        sm[CBS_OFF + p] = b1[p] + b2[p] + b3[p];
        sm[W1S_OFF + p] = W1[p];
    }

    float C[2][4][4];
    #pragma unroll
    for (int mt = 0; mt < 2; ++mt)
        #pragma unroll
        for (int nt = 0; nt < 4; ++nt)
            #pragma unroll
            for (int c = 0; c < 4; ++c) C[mt][nt][c] = 0.f;
    float posr = 0.f, negr = 0.f;

    // ================= mainloop: S = adj @ mu (8 x 64-k chunks) ============
    for (int chunk = 0; chunk < 8; ++chunk) {
        int cur = chunk & 1;
        int k0 = chunk * 64;

        asm volatile("cp.async.wait_group 0;");
        __syncthreads();   // fetch(chunk) visible; all reads of buf cur^1 done

        if (chunk < 7) {
            stage(chunk + 1, cur ^ 1);
            cpasync_commit();
        }

        const float* As_ = sm + AS_OFF + cur * AS_BUF;
        const float* Mu_ = sm + MU_OFF + cur * MU_BUF;

        // pos/neg first (frees wv registers before MMA peak)
        {
            float wv[16];
            #pragma unroll
            for (int s = 0; s < 16; ++s)
                wv[s] = w_b[(size_t)(k0 + ks * 16 + s) * Nn + j0 + jj];
            #pragma unroll
            for (int s = 0; s < 16; ++s) {
                float a = As_[jj * 68 + ks * 16 + s];   // exactly 0/1
                posr += a * fmaxf(wv[s], 0.f);
                negr += a * fmaxf(-wv[s], 0.f);
            }
        }

        // MMA: 4 k16 steps
        #pragma unroll
        for (int kk = 0; kk < 4; ++kk) {
            int kb = kk * 16;
            uint32_t afr[2][4];
            #pragma unroll
            for (int mt = 0; mt < 2; ++mt) {
                int r = warpM * 32 + mt * 16 + g4;
                int c = kb + 2 * t4;
                float2 f0 = *(const float2*)&As_[r * 68 + c];
                float2 f1 = *(const float2*)&As_[(r + 8) * 68 + c];
                float2 f2 = *(const float2*)&As_[r * 68 + c + 8];
                float2 f3 = *(const float2*)&As_[(r + 8) * 68 + c + 8];
                afr[mt][0] = pack_bf16x2(f0.y, f0.x);   // adj exact in bf16
                afr[mt][1] = pack_bf16x2(f1.y, f1.x);
                afr[mt][2] = pack_bf16x2(f2.y, f2.x);
                afr[mt][3] = pack_bf16x2(f3.y, f3.x);
            }
            #pragma unroll
            for (int nt = 0; nt < 4; ++nt) {
                int p = warpN * 32 + nt * 8 + g4;
                float m0 = Mu_[(kb + 2 * t4) * 132 + p];
                float m1 = Mu_[(kb + 2 * t4 + 1) * 132 + p];
                float m2 = Mu_[(kb + 2 * t4 + 8) * 132 + p];
                float m3 = Mu_[(kb + 2 * t4 + 9) * 132 + p];
                uint32_t bh0 = pack_bf16x2(m1, m0);
                uint32_t bh1 = pack_bf16x2(m3, m2);
                uint32_t bl0 = pack_bf16x2(m1 - bf_hi(bh0), m0 - bf_lo(bh0));
                uint32_t bl1 = pack_bf16x2(m3 - bf_hi(bh1), m2 - bf_lo(bh1));
                #pragma unroll
                for (int mt = 0; mt < 2; ++mt) {
                    mma_bf16(C[mt][nt], afr[mt], bh0, bh1);
                    mma_bf16(C[mt][nt], afr[mt], bl0, bl1);
                }
            }
        }
        // no trailing sync: next iter's wait+sync protects buffer reuse
    }

    // ================= pack S -> smem (bf16 hi/lo, k-pair layout) ==========
    __syncthreads();   // mainloop reads done; pipeline region reused
    #pragma unroll
    for (int mt = 0; mt < 2; ++mt) {
        int rb = warpM * 32 + mt * 16;
        #pragma unroll
        for (int nt = 0; nt < 4; ++nt) {
            int kp = warpN * 16 + nt * 4 + t4;
            float c0 = C[mt][nt][0], c1 = C[mt][nt][1];   // row rb+g4
            float c2 = C[mt][nt][2], c3 = C[mt][nt][3];   // row rb+g4+8
            uint32_t h0 = pack_bf16x2(c1, c0);
            uint32_t l0 = pack_bf16x2(c1 - bf_hi(h0), c0 - bf_lo(h0));
            uint32_t h1 = pack_bf16x2(c3, c2);
            uint32_t l1 = pack_bf16x2(c3 - bf_hi(h1), c2 - bf_lo(h1));
            sm[SH_OFF + (rb + g4) * 68 + kp]     = __uint_as_float(h0);
            sm[SL_OFF + (rb + g4) * 68 + kp]     = __uint_as_float(l0);
            sm[SH_OFF + (rb + g4 + 8) * 68 + kp] = __uint_as_float(h1);
            sm[SL_OFF + (rb + g4 + 8) * 68 + kp] = __uint_as_float(l1);
        }
    }

    // ================= D = S @ W2 (two 64-k halves, 3-term split) ==========
    float D[2][4][4];
    #pragma unroll
    for (int mt = 0; mt < 2; ++mt)
        #pragma unroll
        for (int nt = 0; nt < 4; ++nt)
            #pragma unroll
            for (int c = 0; c < 4; ++c) D[mt][nt][c] = 0.f;

    for (int h = 0; h < 2; ++h) {
        __syncthreads();   // S writes done / prev half's W2s reads done
        #pragma unroll
        for (int s = 0; s < 8; ++s) {
            int idx = tid + s * 256;           // 0..2047 float4s
            int k = idx >> 5;
            int c = idx & 31;
            *(float4*)&sm[W2S_OFF + k * 132 + c * 4] =
                *(const float4*)&W2[(size_t)(h * 64 + k) * Pn + c * 4];
        }
        __syncthreads();

        #pragma unroll
        for (int kk2 = 0; kk2 < 4; ++kk2) {
            uint32_t ah[2][4], al[2][4];
            #pragma unroll
            for (int mt = 0; mt < 2; ++mt) {
                int r = warpM * 32 + mt * 16 + g4;
                int base = h * 32 + kk2 * 8 + t4;
                ah[mt][0] = __float_as_uint(sm[SH_OFF + r * 68 + base]);
                ah[mt][1] = __float_as_uint(sm[SH_OFF + (r + 8) * 68 + base]);
                ah[mt][2] = __float_as_uint(sm[SH_OFF + r * 68 + base + 4]);
                ah[mt][3] = __float_as_uint(sm[SH_OFF + (r + 8) * 68 + base + 4]);
                al[mt][0] = __float_as_uint(sm[SL_OFF + r * 68 + base]);
                al[mt][1] = __float_as_uint(sm[SL_OFF + (r + 8) * 68 + base]);
                al[mt][2] = __float_as_uint(sm[SL_OFF + r * 68 + base + 4]);
                al[mt][3] = __float_as_uint(sm[SL_OFF + (r + 8) * 68 + base + 4]);
            }
            #pragma unroll
            for (int nt = 0; nt < 4; ++nt) {
                int p = warpN * 32 + nt * 8 + g4;
                int kl = kk2 * 16 + 2 * t4;
                float w0 = sm[W2S_OFF + kl * 132 + p];
                float w1 = sm[W2S_OFF + (kl + 1) * 132 + p];
                float w2 = sm[W2S_OFF + (kl + 8) * 132 + p];
                float w3 = sm[W2S_OFF + (kl + 9) * 132 + p];
                uint32_t bh0 = pack_bf16x2(w1, w0);
                uint32_t bh1 = pack_bf16x2(w3, w2);
                uint32_t bl0 = pack_bf16x2(w1 - bf_hi(bh0), w0 - bf_lo(bh0));
                uint32_t bl1 = pack_bf16x2(w3 - bf_hi(bh1), w2 - bf_lo(bh1));
                #pragma unroll
                for (int mt = 0; mt < 2; ++mt) {
                    mma_bf16(D[mt][nt], ah[mt], bh0, bh1);
                    mma_bf16(D[mt][nt], ah[mt], bl0, bl1);
                    mma_bf16(D[mt][nt], al[mt], bh0, bh1);
                }
            }
        }
    }

    // ================= pos/neg reduction (deterministic) ===================
    __syncthreads();
    sm[PNB_OFF + ks * 64 + jj]       = posr;
    sm[PNB_OFF + 256 + ks * 64 + jj] = negr;
    __syncthreads();
    if (tid < 64) {
        const float* p = sm + PNB_OFF;
        sm[POS_OFF + tid] = (p[tid] + p[64 + tid]) + (p[128 + tid] + p[192 + tid]);
    } else if (tid < 128) {
        int j = tid - 64;
        const float* p = sm + PNB_OFF + 256;
        sm[NEG_OFF + j] = (p[j] + p[64 + j]) + (p[128 + j] + p[192 + j]);
    }
    __syncthreads();

    // ================= final epilogue ======================================
    const float* W1s = sm + W1S_OFF;
    const float* vps = sm + VPS_OFF;
    const float* vns = sm + VNS_OFF;
    const float* cbs = sm + CBS_OFF;
    #pragma unroll
    for (int mt = 0; mt < 2; ++mt) {
        #pragma unroll
        for (int half = 0; half < 2; ++half) {
            int j = warpM * 32 + mt * 16 + g4 + half * 8;
            int gj = j0 + j;
            float xv = x[b * Nn + gj];
            float pj = sm[POS_OFF + j];
            float nj = sm[NEG_OFF + j];
            #pragma unroll
            for (int nt = 0; nt < 4; ++nt) {
                int p = warpN * 32 + nt * 8 + 2 * t4;
                float c0 = D[mt][nt][half * 2 + 0];
                float c1 = D[mt][nt][half * 2 + 1];
                float2 o;
                o.x = fmaxf(xv * W1s[p] + c0 + pj * vps[p] + nj * vns[p] + cbs[p], 0.f);
                o.y = fmaxf(xv * W1s[p + 1] + c1 + pj * vps[p + 1] + nj * vns[p + 1] + cbs[p + 1], 0.f);
                *(float2*)&out[((size_t)b * Nn + gj) * Pn + p] = o;
            }
        }
    }
}

// ---------------------------------------------------------------------------
extern "C" void kernel_launch(void* const* d_in, const int* in_sizes, int n_in,
                              void* d_out, int out_size) {
    const float* x      = (const float*)d_in[0];
    const float* mu     = (const float*)d_in[1];
    const float* weight = (const float*)d_in[2];
    const float* adj    = (const float*)d_in[3];
    const float* W1     = (const float*)d_in[4];
    const float* b1     = (const float*)d_in[5];
    const float* W2     = (const float*)d_in[6];
    const float* b2     = (const float*)d_in[7];
    const float* W3     = (const float*)d_in[8];
    const float* b3     = (const float*)d_in[9];
    const float* theta4 = (const float*)d_in[10];
    float* out = (float*)d_out;

    const int smem_bytes = SMF_TOT * 4;   // 107008 B
    static int configured = -1;
    if (configured < 0) {
        cudaFuncSetAttribute(s2v_kernel,
                             cudaFuncAttributeMaxDynamicSharedMemorySize,
                             smem_bytes);
        configured = 1;
    }

    dim3 grid(Nn / 64, Bn);
    s2v_kernel<<<grid, 256, smem_bytes>>>(adj, weight, mu, x, W1, W2, W3,
                                          theta4, b1, b2, b3, out);
}

// round 15
// speedup vs baseline: 2.9063x; 1.0124x over previous
#include <cuda_runtime.h>
#include <stdint.h>

#define Bn 32
#define Nn 512
#define Pn 128

// ---- helpers --------------------------------------------------------------
__device__ __forceinline__ uint32_t pack_bf16x2(float hi, float lo) {
    uint32_t d;
    asm("cvt.rn.bf16x2.f32 %0, %1, %2;" : "=r"(d) : "f"(hi), "f"(lo));
    return d;
}
__device__ __forceinline__ float bf_lo(uint32_t u) {
    return __uint_as_float(u << 16);
}
__device__ __forceinline__ float bf_hi(uint32_t u) {
    return __uint_as_float(u & 0xFFFF0000u);
}

// bf16 mma m16n8k16: D(fp32) += A(bf16) @ B(bf16)
__device__ __forceinline__ void mma_bf16(float* c, const uint32_t* a,
                                         uint32_t b0, uint32_t b1) {
    asm volatile(
        "mma.sync.aligned.m16n8k16.row.col.f32.bf16.bf16.f32 "
        "{%0,%1,%2,%3}, {%4,%5,%6,%7}, {%8,%9}, {%0,%1,%2,%3};"
        : "+f"(c[0]), "+f"(c[1]), "+f"(c[2]), "+f"(c[3])
        : "r"(a[0]), "r"(a[1]), "r"(a[2]), "r"(a[3]), "r"(b0), "r"(b1));
}

__device__ __forceinline__ void cpasync16(uint32_t dst, const void* src) {
    asm volatile("cp.async.cg.shared.global [%0], [%1], 16;"
                 :: "r"(dst), "l"(src));
}
__device__ __forceinline__ void cpasync_commit() {
    asm volatile("cp.async.commit_group;");
}

// ---------------------------------------------------------------------------
// Single fused kernel. Grid (8 j-tiles, 32 b) x 256 threads (8 warps: 2M x 4N).
//   S[64 j][128 k'] = adj @ mu   (bf16-split MMA, 64-k chunks, 1 sync/iter,
//                                 pos/neg LDGs interleaved under MMA)
//   D = S @ W2                   (single 128-k pass; W2 staged via cp.async
//                                 overlapped with mainloop tail + S-pack)
//   out = relu(x*W1 + D + pos*vp + neg*vn + cb)
//
// smem (float units), ~107 KB -> 2 CTA/SM:
//   pipeline: As 2x[64][68]=8704 | Mu 2x[64][132]=16896
//   epilogue overlay: Sh [64][68] | Sl [64][68] | W2s [128][132]=16896
//     (W2 half0 lands in dead Mu-buf0 during chunk 7; half1 after mainloop)
// ---------------------------------------------------------------------------
#define AS_OFF  0
#define AS_BUF  4352
#define MU_OFF  8704
#define MU_BUF  8448
#define SH_OFF  0
#define SL_OFF  4352
#define W2S_OFF 8704
#define W1S_OFF 25600
#define VPS_OFF 25728
#define VNS_OFF 25856
#define CBS_OFF 25984
#define PNB_OFF 26112
#define POS_OFF 26624
#define NEG_OFF 26688
#define SMF_TOT 26752

__global__ __launch_bounds__(256, 2) void s2v_kernel(
    const float* __restrict__ adj, const float* __restrict__ weight,
    const float* __restrict__ mu, const float* __restrict__ x,
    const float* __restrict__ W1, const float* __restrict__ W2,
    const float* __restrict__ W3, const float* __restrict__ theta4,
    const float* __restrict__ b1, const float* __restrict__ b2,
    const float* __restrict__ b3, float* __restrict__ out) {
    extern __shared__ float sm[];
    uint32_t smu = (uint32_t)__cvta_generic_to_shared(sm);

    int tid = threadIdx.x;
    int warp = tid >> 5;
    int lane = tid & 31;
    int warpM = warp >> 2;            // 0..1
    int warpN = warp & 3;             // 0..3
    int g4 = lane >> 2;               // 0..7
    int t4 = lane & 3;                // 0..3
    int b = blockIdx.y;
    int j0 = blockIdx.x * 64;

    const float* adj_b = adj + (size_t)b * Nn * Nn;
    const float* w_b   = weight + (size_t)b * Nn * Nn;
    const float* mu_b  = mu + (size_t)b * Nn * Pn;

    int jj = tid & 63;                // pos/neg column
    int ks = tid >> 6;                // 0..3 -> k-subrange ks*16..+15

    // ---- staging: one 64-k chunk (12 x 16B cp.async per thread) ----
    auto stage = [&](int chunk, int buf) {
        int k0 = chunk * 64;
        uint32_t asb = smu + (AS_OFF + buf * AS_BUF) * 4;
        #pragma unroll
        for (int s = 0; s < 4; ++s) {
            int idx = tid + s * 256;           // 0..1023
            int row = idx >> 4;
            int q = idx & 15;
            cpasync16(asb + (row * 68 + q * 4) * 4,
                      &adj_b[(size_t)(j0 + row) * Nn + k0 + q * 4]);
        }
        uint32_t mub = smu + (MU_OFF + buf * MU_BUF) * 4;
        #pragma unroll
        for (int s = 0; s < 8; ++s) {
            int idx = tid + s * 256;           // 0..2047
            int k = idx >> 5;
            int c = idx & 31;
            cpasync16(mub + (k * 132 + c * 4) * 4,
                      &mu_b[(size_t)(k0 + k) * Pn + c * 4]);
        }
    };
    // ---- W2 half staging into overlay (rows h*64..h*64+63) ----
    auto stage_w2 = [&](int h) {
        #pragma unroll
        for (int s = 0; s < 8; ++s) {
            int idx = tid + s * 256;           // 0..2047
            int k = idx >> 5;
            int c = idx & 31;
            cpasync16(smu + (W2S_OFF + (h * 64 + k) * 132 + c * 4) * 4,
                      &W2[(size_t)(h * 64 + k) * Pn + c * 4]);
        }
    };

    stage(0, 0);
    cpasync_commit();

    // ---- prep (overlapped with chunk-0 fill): vp/vn/cb/W1 ----
    if (tid < 128) {
        int p = tid;
        float vp = 0.f, vn = 0.f;
        #pragma unroll 8
        for (int q = 0; q < Pn; ++q) {
            float t = theta4[q];
            float w = W3[q * Pn + p];
            vp += fmaxf(t, 0.f) * w;
            vn += fmaxf(-t, 0.f) * w;
        }
        sm[VPS_OFF + p] = vp;
        sm[VNS_OFF + p] = vn;
        sm[CBS_OFF + p] = b1[p] + b2[p] + b3[p];
        sm[W1S_OFF + p] = W1[p];
    }

    float C[2][4][4];
    #pragma unroll
    for (int mt = 0; mt < 2; ++mt)
        #pragma unroll
        for (int nt = 0; nt < 4; ++nt)
            #pragma unroll
            for (int c = 0; c < 4; ++c) C[mt][nt][c] = 0.f;
    float posr = 0.f, negr = 0.f;

    // ================= mainloop: S = adj @ mu (8 x 64-k chunks) ============
    for (int chunk = 0; chunk < 8; ++chunk) {
        int cur = chunk & 1;
        int k0 = chunk * 64;

        asm volatile("cp.async.wait_group 0;");
        __syncthreads();   // fetch(chunk) visible; all reads of buf cur^1 done

        if (chunk < 7) {
            stage(chunk + 1, cur ^ 1);
            cpasync_commit();
        } else {
            stage_w2(0);   // W2 rows 0..63 -> dead Mu-buf0 region
            cpasync_commit();
        }

        const float* As_ = sm + AS_OFF + cur * AS_BUF;
        const float* Mu_ = sm + MU_OFF + cur * MU_BUF;

        // MMA with interleaved pos/neg (LDG latency hidden under MMA work)
        #pragma unroll
        for (int half = 0; half < 2; ++half) {
            // prefetch 8 weight values (independent LDGs)
            float wv[8];
            #pragma unroll
            for (int s = 0; s < 8; ++s)
                wv[s] = w_b[(size_t)(k0 + ks * 16 + half * 8 + s) * Nn + j0 + jj];

            #pragma unroll
            for (int kk = half * 2; kk < half * 2 + 2; ++kk) {
                int kb = kk * 16;
                uint32_t afr[2][4];
                #pragma unroll
                for (int mt = 0; mt < 2; ++mt) {
                    int r = warpM * 32 + mt * 16 + g4;
                    int c = kb + 2 * t4;
                    float2 f0 = *(const float2*)&As_[r * 68 + c];
                    float2 f1 = *(const float2*)&As_[(r + 8) * 68 + c];
                    float2 f2 = *(const float2*)&As_[r * 68 + c + 8];
                    float2 f3 = *(const float2*)&As_[(r + 8) * 68 + c + 8];
                    afr[mt][0] = pack_bf16x2(f0.y, f0.x);   // adj exact in bf16
                    afr[mt][1] = pack_bf16x2(f1.y, f1.x);
                    afr[mt][2] = pack_bf16x2(f2.y, f2.x);
                    afr[mt][3] = pack_bf16x2(f3.y, f3.x);
                }
                #pragma unroll
                for (int nt = 0; nt < 4; ++nt) {
                    int p = warpN * 32 + nt * 8 + g4;
                    float m0 = Mu_[(kb + 2 * t4) * 132 + p];
                    float m1 = Mu_[(kb + 2 * t4 + 1) * 132 + p];
                    float m2 = Mu_[(kb + 2 * t4 + 8) * 132 + p];
                    float m3 = Mu_[(kb + 2 * t4 + 9) * 132 + p];
                    uint32_t bh0 = pack_bf16x2(m1, m0);
                    uint32_t bh1 = pack_bf16x2(m3, m2);
                    uint32_t bl0 = pack_bf16x2(m1 - bf_hi(bh0), m0 - bf_lo(bh0));
                    uint32_t bl1 = pack_bf16x2(m3 - bf_hi(bh1), m2 - bf_lo(bh1));
                    #pragma unroll
                    for (int mt = 0; mt < 2; ++mt) {
                        mma_bf16(C[mt][nt], afr[mt], bh0, bh1);
                        mma_bf16(C[mt][nt], afr[mt], bl0, bl1);
                    }
                }
            }

            // consume pos/neg (adj mask from staged A tile; exactly 0/1)
            #pragma unroll
            for (int s = 0; s < 8; ++s) {
                float a = As_[jj * 68 + ks * 16 + half * 8 + s];
                posr += a * fmaxf(wv[s], 0.f);
                negr += a * fmaxf(-wv[s], 0.f);
            }
        }
        // no trailing sync: next iter's wait+sync protects buffer reuse
    }

    // ================= pack S -> smem; W2 half1 staged under it ============
    __syncthreads();   // mainloop reads done (Mu-buf1, As bufs now dead)
    stage_w2(1);       // W2 rows 64..127 -> former Mu-buf1 region
    cpasync_commit();

    #pragma unroll
    for (int mt = 0; mt < 2; ++mt) {
        int rb = warpM * 32 + mt * 16;
        #pragma unroll
        for (int nt = 0; nt < 4; ++nt) {
            int kp = warpN * 16 + nt * 4 + t4;
            float c0 = C[mt][nt][0], c1 = C[mt][nt][1];   // row rb+g4
            float c2 = C[mt][nt][2], c3 = C[mt][nt][3];   // row rb+g4+8
            uint32_t h0 = pack_bf16x2(c1, c0);
            uint32_t l0 = pack_bf16x2(c1 - bf_hi(h0), c0 - bf_lo(h0));
            uint32_t h1 = pack_bf16x2(c3, c2);
            uint32_t l1 = pack_bf16x2(c3 - bf_hi(h1), c2 - bf_lo(h1));
            sm[SH_OFF + (rb + g4) * 68 + kp]     = __uint_as_float(h0);
            sm[SL_OFF + (rb + g4) * 68 + kp]     = __uint_as_float(l0);
            sm[SH_OFF + (rb + g4 + 8) * 68 + kp] = __uint_as_float(h1);
            sm[SL_OFF + (rb + g4 + 8) * 68 + kp] = __uint_as_float(l1);
        }
    }

    // ================= D = S @ W2 (single 128-k pass, 3-term split) ========
    float D[2][4][4];
    #pragma unroll
    for (int mt = 0; mt < 2; ++mt)
        #pragma unroll
        for (int nt = 0; nt < 4; ++nt)
            #pragma unroll
            for (int c = 0; c < 4; ++c) D[mt][nt][c] = 0.f;

    asm volatile("cp.async.wait_group 0;");
    __syncthreads();   // W2 staged + S-pack visible

    #pragma unroll
    for (int kk2 = 0; kk2 < 8; ++kk2) {
        uint32_t ah[2][4], al[2][4];
        #pragma unroll
        for (int mt = 0; mt < 2; ++mt) {
            int r = warpM * 32 + mt * 16 + g4;
            int base = kk2 * 8 + t4;
            ah[mt][0] = __float_as_uint(sm[SH_OFF + r * 68 + base]);
            ah[mt][1] = __float_as_uint(sm[SH_OFF + (r + 8) * 68 + base]);
            ah[mt][2] = __float_as_uint(sm[SH_OFF + r * 68 + base + 4]);
            ah[mt][3] = __float_as_uint(sm[SH_OFF + (r + 8) * 68 + base + 4]);
            al[mt][0] = __float_as_uint(sm[SL_OFF + r * 68 + base]);
            al[mt][1] = __float_as_uint(sm[SL_OFF + (r + 8) * 68 + base]);
            al[mt][2] = __float_as_uint(sm[SL_OFF + r * 68 + base + 4]);
            al[mt][3] = __float_as_uint(sm[SL_OFF + (r + 8) * 68 + base + 4]);
        }
        #pragma unroll
        for (int nt = 0; nt < 4; ++nt) {
            int p = warpN * 32 + nt * 8 + g4;
            int kl = kk2 * 16 + 2 * t4;
            float w0 = sm[W2S_OFF + kl * 132 + p];
            float w1 = sm[W2S_OFF + (kl + 1) * 132 + p];
            float w2 = sm[W2S_OFF + (kl + 8) * 132 + p];
            float w3 = sm[W2S_OFF + (kl + 9) * 132 + p];
            uint32_t bh0 = pack_bf16x2(w1, w0);
            uint32_t bh1 = pack_bf16x2(w3, w2);
            uint32_t bl0 = pack_bf16x2(w1 - bf_hi(bh0), w0 - bf_lo(bh0));
            uint32_t bl1 = pack_bf16x2(w3 - bf_hi(bh1), w2 - bf_lo(bh1));
            #pragma unroll
            for (int mt = 0; mt < 2; ++mt) {
                mma_bf16(D[mt][nt], ah[mt], bh0, bh1);
                mma_bf16(D[mt][nt], ah[mt], bl0, bl1);
                mma_bf16(D[mt][nt], al[mt], bh0, bh1);
            }
        }
    }

    // ================= pos/neg reduction (deterministic) ===================
    __syncthreads();
    sm[PNB_OFF + ks * 64 + jj]       = posr;
    sm[PNB_OFF + 256 + ks * 64 + jj] = negr;
    __syncthreads();
    if (tid < 64) {
        const float* p = sm + PNB_OFF;
        sm[POS_OFF + tid] = (p[tid] + p[64 + tid]) + (p[128 + tid] + p[192 + tid]);
    } else if (tid < 128) {
        int j = tid - 64;
        const float* p = sm + PNB_OFF + 256;
        sm[NEG_OFF + j] = (p[j] + p[64 + j]) + (p[128 + j] + p[192 + j]);
    }
    __syncthreads();

    // ================= final epilogue ======================================
    const float* W1s = sm + W1S_OFF;
    const float* vps = sm + VPS_OFF;
    const float* vns = sm + VNS_OFF;
    const float* cbs = sm + CBS_OFF;
    #pragma unroll
    for (int mt = 0; mt < 2; ++mt) {
        #pragma unroll
        for (int half = 0; half < 2; ++half) {
            int j = warpM * 32 + mt * 16 + g4 + half * 8;
            int gj = j0 + j;
            float xv = x[b * Nn + gj];
            float pj = sm[POS_OFF + j];
            float nj = sm[NEG_OFF + j];
            #pragma unroll
            for (int nt = 0; nt < 4; ++nt) {
                int p = warpN * 32 + nt * 8 + 2 * t4;
                float c0 = D[mt][nt][half * 2 + 0];
                float c1 = D[mt][nt][half * 2 + 1];
                float2 o;
                o.x = fmaxf(xv * W1s[p] + c0 + pj * vps[p] + nj * vns[p] + cbs[p], 0.f);
                o.y = fmaxf(xv * W1s[p + 1] + c1 + pj * vps[p + 1] + nj * vns[p + 1] + cbs[p + 1], 0.f);
                *(float2*)&out[((size_t)b * Nn + gj) * Pn + p] = o;
            }
        }
    }
}

// ---------------------------------------------------------------------------
extern "C" void kernel_launch(void* const* d_in, const int* in_sizes, int n_in,
                              void* d_out, int out_size) {
    const float* x      = (const float*)d_in[0];
    const float* mu     = (const float*)d_in[1];
    const float* weight = (const float*)d_in[2];
    const float* adj    = (const float*)d_in[3];
    const float* W1     = (const float*)d_in[4];
    const float* b1     = (const float*)d_in[5];
    const float* W2     = (const float*)d_in[6];
    const float* b2     = (const float*)d_in[7];
    const float* W3     = (const float*)d_in[8];
    const float* b3     = (const float*)d_in[9];
    const float* theta4 = (const float*)d_in[10];
    float* out = (float*)d_out;

    const int smem_bytes = SMF_TOT * 4;   // 107008 B
    static int configured = -1;
    if (configured < 0) {
        cudaFuncSetAttribute(s2v_kernel,
                             cudaFuncAttributeMaxDynamicSharedMemorySize,
                             smem_bytes);
        configured = 1;
    }

    dim3 grid(Nn / 64, Bn);
    s2v_kernel<<<grid, 256, smem_bytes>>>(adj, weight, mu, x, W1, W2, W3,
                                          theta4, b1, b2, b3, out);
}